// round 14
// baseline (speedup 1.0000x reference)
#include <cuda_runtime.h>
#include <cuda_fp16.h>
#include <cstdint>

// Problem constants (fixed by the reference)
#define NN 10000          // nodes
#define DD 784            // input feat dim
#define KPAD 800          // DD padded to multiple of 32 (pad cols stay zero)
#define KK 16             // neighbors+1
#define EE (NN * (KK-1))  // edges = 150000
#define HH 128            // hidden width

// ============================ scratch globals ===============================
// Numeric scheme (FROZEN since R12): A-side exact via fp16 hi/lo pair;
// B-side (weights) single fp16. GEMM computes (Ah+Al)@Bh -> 2 MMA products.
__device__ __align__(256) __half g_xh   [NN * KPAD];
__device__ __align__(256) __half g_xl   [NN * KPAD];
__device__ __align__(256) __half g_Wt1h [256 * KPAD]; // [l1 msgW1x^T ; l1 nodeW1a^T]
__device__ __align__(256) __half g_Wf1h [HH * HH];    // (l1 msgW2 @ l1 nodeW1b)^T
__device__ __align__(256) __half g_Wf2h [HH * HH];
__device__ __align__(256) __half g_Whth [256 * HH];   // (l1 nodeW2 @ [l2 W1x | l2 W1a])^T
__device__ __align__(256) float g_bf1[HH];
__device__ __align__(256) float g_bf2[HH];
__device__ __align__(256) float g_bh [256];
__device__ __align__(256) float g_XW  [NN * 256];   // split-K part 0
__device__ __align__(256) float g_XW2 [NN * 256];   // split-K part 1
__device__ __align__(256) float g_HW2 [NN * 256];
__device__ __align__(256) __half g_hbh [NN * HH];     // hbar hi/lo
__device__ __align__(256) __half g_hbl [NN * HH];
__device__ __align__(256) __half g_hidh[NN * HH];     // hidden hi/lo
__device__ __align__(256) __half g_hidl[NN * HH];
__device__ __align__(256) float g_proj[NN * 2];
__device__ int   g_csr [2 * NN + 1];   // [cnt | pos | counter] -> ONE memset
__device__ int   g_offs[NN];
__device__ __align__(256) float g_bucket[EE];

// ============================ prep megakernel ===============================
struct FoldArgs {
    const float* A[4];
    const float* avec[4];
    const float* B[4];
    __half* oh[4];
    float* bf[4];
    int Kd[4];
    int row_off[4];
};

#define PB_COUNT 586
#define PB_CONV  7657
#define PB_CONVT 1024     // 2 weights x (4 k-blocks x 128 n)
#define PB_FOLD  516      // 4 folds x 129 rows
#define PB_TOTAL (PB_COUNT + PB_CONV + PB_CONVT + PB_FOLD)

__global__ void __launch_bounds__(256)
prep_mega(const int* __restrict__ idxs, const float* __restrict__ x,
          const float* __restrict__ Wc0, const float* __restrict__ Wc1,
          __half* __restrict__ xh, __half* __restrict__ xl,
          __half* __restrict__ Wt1h, FoldArgs fa) {
    __shared__ float red[256];
    int b = blockIdx.x, tid = threadIdx.x;

    if (b < PB_COUNT) {                       // ---- edge count ----
        int e = b * 256 + tid;
        if (e < EE) atomicAdd(&g_csr[idxs[e]], 1);
        return;
    }
    b -= PB_COUNT;
    if (b < PB_CONV) {                        // ---- x fp16 hi/lo split ----
        int i = b * 256 + tid;
        if (i >= NN * (DD / 4)) return;
        int row = i / (DD / 4), c = i % (DD / 4);
        float4 v = ((const float4*)(x + (size_t)row * DD))[c];
        __half h0 = __float2half(v.x), h1 = __float2half(v.y);
        __half h2 = __float2half(v.z), h3 = __float2half(v.w);
        __half l0 = __float2half(v.x - __half2float(h0));
        __half l1 = __float2half(v.y - __half2float(h1));
        __half l2 = __float2half(v.z - __half2float(h2));
        __half l3 = __float2half(v.w - __half2float(h3));
        size_t o = (size_t)row * KPAD + c * 4;
        *(__half2*)(xh + o)     = __half2(h0, h1);
        *(__half2*)(xh + o + 2) = __half2(h2, h3);
        *(__half2*)(xl + o)     = __half2(l0, l1);
        *(__half2*)(xl + o + 2) = __half2(l2, l3);
        return;
    }
    b -= PB_CONV;
    if (b < PB_CONVT) {                       // ---- W1 transpose, fp16 hi ----
        int z = b >> 9;                       // which weight (0/1)
        int rem = b & 511;
        int kb = rem & 3, n = rem >> 2;
        int k = kb * 256 + tid;
        if (k >= DD) return;
        const float* W = z ? Wc1 : Wc0;
        float v = W[(size_t)k * 128 + n];
        Wt1h[(size_t)(z * 128 + n) * KPAD + k] = __float2half(v);
        return;
    }
    b -= PB_CONVT;
    {                                         // ---- weight folds (fp16 hi) ----
        int f = b / 129, i = b % 129;
        int j = tid & 127, kq = tid >> 7;     // 2-way K split
        int Kd = fa.Kd[f];
        const float* arow = (i < 128) ? (fa.A[f] + (size_t)i * Kd) : fa.avec[f];
        const float* B = fa.B[f];
        int chunk = (Kd + 1) >> 1;
        int k0 = kq * chunk, k1 = min(Kd, k0 + chunk);
        float s = 0.f;
        #pragma unroll 4
        for (int k = k0; k < k1; k++)
            s = fmaf(__ldg(&arow[k]), B[(size_t)k * HH + j], s);
        red[tid] = s;
        __syncthreads();
        if (kq == 0) {
            s = red[j] + red[128 + j];
            if (i < 128)
                fa.oh[f][(size_t)(fa.row_off[f] + j) * HH + i] = __float2half(s);
            else
                fa.bf[f][j] = s;
        }
        return;
    }
}

// offsets need only be disjoint ranges, not ordered -> block scan + atomic base
__global__ void offs_kernel() {
    __shared__ int sd[256];
    __shared__ int base_s;
    int t = threadIdx.x;
    int i = blockIdx.x * 256 + t;
    int v = (i < NN) ? g_csr[i] : 0;
    sd[t] = v;
    __syncthreads();
    #pragma unroll
    for (int o = 1; o < 256; o <<= 1) {
        int x = (t >= o) ? sd[t - o] : 0;
        __syncthreads();
        sd[t] += x;
        __syncthreads();
    }
    if (t == 255) base_s = atomicAdd(&g_csr[2 * NN], sd[255]);
    __syncthreads();
    if (i < NN) g_offs[i] = base_s + sd[t] - v;
}

__global__ void fill_kernel(const int* __restrict__ idxs,
                            const float* __restrict__ ea) {
    int e = blockIdx.x * blockDim.x + threadIdx.x;
    if (e < EE) {
        int s = idxs[e];
        int p = atomicAdd(&g_csr[NN + s], 1);
        g_bucket[g_offs[s] + p] = ea[e];
    }
}

// flat per-(node,col) edge aggregation; optional second split-K buffer:
// hbar[m,j] = mean_e relu(xwA[m,j] (+ xwB[m,j]) + b[j] (+ b2[j]) + a_e*we[j])
__global__ void edge_agg(const float* __restrict__ xwA,
                         const float* __restrict__ xwB, int ld,
                         const float* __restrict__ we,
                         const float* __restrict__ b,
                         const float* __restrict__ b2,
                         __half* __restrict__ oh,
                         __half* __restrict__ ol) {
    int idx = blockIdx.x * blockDim.x + threadIdx.x;
    if (idx >= NN * HH) return;
    int m = idx >> 7;
    int j = idx & 127;
    int deg = g_csr[m];
    int start = g_offs[m];
    float xj = xwA[(size_t)m * ld + j] + __ldg(&b[j]);
    if (xwB) xj += xwB[(size_t)m * ld + j];
    if (b2)  xj += __ldg(&b2[j]);
    float wj = __ldg(&we[j]);
    float s = 0.f;
    for (int t = 0; t < deg; t++)
        s += fmaxf(fmaf(g_bucket[start + t], wj, xj), 0.f);
    float v = deg ? s / (float)deg : 0.f;
    __half h = __float2half(v);
    oh[(size_t)m * HH + j] = h;
    ol[(size_t)m * HH + j] = __float2half(v - __half2float(h));
}

// ============================ mma.sync GEMM ================================
// C[M,Ntot] = (Ah+Al)[M,K] @ Bh^T (B stored [Ntot][K] fp16); 2-product.
// Block tile 64xBN, BK=32, 8 warps (2 M x 4 N), STAGES-deep cp.async pipeline,
// MB min-blocks occupancy bound. Optional split-K via gridDim.z==2.
// Fused projection (projOut != nullptr) accumulates partial row-projections
// via global atomicAdd (projOut must be pre-zeroed; projB added by block x==0).
#define TPITCH 40                      // fp16 pitch (80 B) per smem tile row
#define TILE_A (64 * TPITCH * 2)       // 5120 B

__device__ __forceinline__ uint32_t smem_u32(const void* p) {
    uint32_t a;
    asm("{ .reg .u64 t; cvta.to.shared.u64 t, %1; cvt.u32.u64 %0, t; }"
        : "=r"(a) : "l"(p));
    return a;
}
__device__ __forceinline__ void cp16(uint32_t dst, const void* src, int sz) {
    asm volatile("cp.async.cg.shared.global [%0], [%1], 16, %2;"
        :: "r"(dst), "l"(src), "r"(sz) : "memory");
}
__device__ __forceinline__ void ldsm_x4(uint32_t* r, uint32_t a) {
    asm volatile("ldmatrix.sync.aligned.m8n8.x4.shared.b16 {%0,%1,%2,%3}, [%4];"
        : "=r"(r[0]), "=r"(r[1]), "=r"(r[2]), "=r"(r[3]) : "r"(a));
}
__device__ __forceinline__ void mma_f16(float* c, const uint32_t* a, const uint32_t* b) {
    asm volatile("mma.sync.aligned.m16n8k16.row.col.f32.f16.f16.f32 "
        "{%0,%1,%2,%3}, {%4,%5,%6,%7}, {%8,%9}, {%0,%1,%2,%3};"
        : "+f"(c[0]), "+f"(c[1]), "+f"(c[2]), "+f"(c[3])
        : "r"(a[0]), "r"(a[1]), "r"(a[2]), "r"(a[3]), "r"(b[0]), "r"(b[1]));
}

template<int BN, int STAGES, int MB>
__global__ void __launch_bounds__(256, MB)
tgemm(const __half* __restrict__ Ah, const __half* __restrict__ Al,
      int lda,
      const __half* __restrict__ Bh, int ldb, int K, int M,
      float* __restrict__ C, float* __restrict__ C2, int ksplit, int ldc,
      const float* __restrict__ bias,
      const float* __restrict__ cbias, const int* __restrict__ cnt,
      const float* __restrict__ addend, const float* __restrict__ addend2,
      int addld, int relu,
      __half* __restrict__ outHi, __half* __restrict__ outLo,
      const float* __restrict__ projW, const float* __restrict__ projB,
      float* __restrict__ projOut) {
    constexpr int TILE_Bn = BN * TPITCH * 2;
    constexpr int STG_B = 2 * TILE_A + TILE_Bn;
    constexpr int NI = BN / 32;        // fragment column groups
    constexpr int NP = NI / 2;         // ldsm_x4 B loads per ks
    constexpr int WCW = BN / 4;        // cols per N-warp
    constexpr int NCH = 512 + BN * 4;  // 16B chunks per stage
    constexpr int U = NCH / 256;

    extern __shared__ char smem[];
    uint32_t sb = smem_u32(smem);
    int tid = threadIdx.x;
    int wid = tid >> 5, lane = tid & 31;
    int bm = blockIdx.y * 64;
    int bn = blockIdx.x * BN;
    int wr = wid & 1;        // M warp (0..1), 32 rows each
    int wc = wid >> 1;       // N warp (0..3), WCW cols each

    // split-K resolution
    int kb = 0, ke = K;
    float* Cw = C;
    if (gridDim.z == 2) {
        if (blockIdx.z == 1) { kb = ksplit; Cw = C2; }
        else                 { ke = ksplit; }
    }
    const __half* srcs[3] = {Ah + kb, Al + kb, Bh + kb};
    const int toff[3] = {0, TILE_A, 2 * TILE_A};

    auto issue = [&](int kc, int stg) {
        int k0 = kc * 32;
        #pragma unroll
        for (int u = 0; u < U; u++) {
            int idx = tid + u * 256;
            int tile, row;
            if (idx < 256)      { tile = 0; row = idx >> 2; }
            else if (idx < 512) { tile = 1; row = (idx - 256) >> 2; }
            else                { tile = 2; row = (idx - 512) >> 2; }
            int c = idx & 3;
            int gr, maxr;
            if (tile < 2) { gr = bm + row; maxr = M; }
            else          { gr = bn + row; maxr = 1 << 30; }
            const __half* s = srcs[tile] +
                (size_t)gr * ((tile < 2) ? lda : ldb) + k0 + c * 8;
            uint32_t d = sb + stg * STG_B + toff[tile] + row * (TPITCH * 2) + c * 16;
            cp16(d, s, (gr < maxr) ? 16 : 0);
        }
        asm volatile("cp.async.commit_group;" ::: "memory");
    };

    float acc[2][NI][4] = {};
    int nT = (ke - kb) / 32;

    issue(0, 0);
    for (int t = 0; t < nT; t++) {
        int stg = t % STAGES;
        if (t + 1 < nT) {
            issue(t + 1, (t + 1) % STAGES);
            asm volatile("cp.async.wait_group 1;" ::: "memory");
        } else {
            asm volatile("cp.async.wait_group 0;" ::: "memory");
        }
        __syncthreads();

        uint32_t baseAH = sb + stg * STG_B + toff[0];
        uint32_t baseAL = sb + stg * STG_B + toff[1];
        uint32_t baseBH = sb + stg * STG_B + toff[2];

        #pragma unroll
        for (int ks = 0; ks < 2; ks++) {
            uint32_t aH[2][4], aL[2][4], bH[NP][4];
            int acol = (ks * 16 + (lane >> 4) * 8) * 2;
            int bcol = (ks * 16 + ((lane >> 3) & 1) * 8) * 2;
            #pragma unroll
            for (int mi = 0; mi < 2; mi++) {
                int arow = wr * 32 + mi * 16 + (lane & 15);
                ldsm_x4(aH[mi], baseAH + arow * (TPITCH * 2) + acol);
                ldsm_x4(aL[mi], baseAL + arow * (TPITCH * 2) + acol);
            }
            #pragma unroll
            for (int np = 0; np < NP; np++) {
                int brow = wc * WCW + np * 16 + ((lane >> 4) & 1) * 8 + (lane & 7);
                ldsm_x4(bH[np], baseBH + brow * (TPITCH * 2) + bcol);
            }
            #pragma unroll
            for (int mi = 0; mi < 2; mi++)
                #pragma unroll
                for (int ni = 0; ni < NI; ni++) {
                    const uint32_t* bh_ = &bH[ni >> 1][(ni & 1) * 2];
                    mma_f16(acc[mi][ni], aH[mi], bh_);
                    mma_f16(acc[mi][ni], aL[mi], bh_);
                }
        }
        __syncthreads();
    }

    // ---- epilogue ----
    float* pbuf = (float*)smem;               // 64 rows x 2 proj accumulators
    if (projOut) {
        for (int i = tid; i < 128; i += 256) pbuf[i] = 0.f;
        __syncthreads();
    }
    float pacc[2][2][2] = {};
    #pragma unroll
    for (int mi = 0; mi < 2; mi++) {
        #pragma unroll
        for (int half = 0; half < 2; half++) {
            int gm = bm + wr * 32 + mi * 16 + (lane >> 2) + half * 8;
            if (gm >= M) continue;
            bool cb = (cbias != nullptr) && (cnt[gm] > 0);
            #pragma unroll
            for (int ni = 0; ni < NI; ni++) {
                #pragma unroll
                for (int e = 0; e < 2; e++) {
                    int gn = bn + wc * WCW + ni * 8 + (lane & 3) * 2 + e;
                    float v = acc[mi][ni][half * 2 + e];
                    if (bias)    v += __ldg(&bias[gn]);
                    if (cb)      v += __ldg(&cbias[gn]);
                    if (addend)  v += addend[(size_t)gm * addld + gn];
                    if (addend2) v += addend2[(size_t)gm * addld + gn];
                    if (relu)    v = fmaxf(v, 0.f);
                    if (Cw) Cw[(size_t)gm * ldc + gn] = v;
                    if (outHi) {
                        __half h = __float2half(v);
                        outHi[(size_t)gm * 128 + gn] = h;
                        outLo[(size_t)gm * 128 + gn] =
                            __float2half(v - __half2float(h));
                    }
                    if (projOut) {
                        pacc[mi][half][0] = fmaf(v, __ldg(&projW[gn * 2 + 0]),
                                                 pacc[mi][half][0]);
                        pacc[mi][half][1] = fmaf(v, __ldg(&projW[gn * 2 + 1]),
                                                 pacc[mi][half][1]);
                    }
                }
            }
        }
    }
    if (projOut) {
        #pragma unroll
        for (int mi = 0; mi < 2; mi++)
            #pragma unroll
            for (int half = 0; half < 2; half++) {
                int rl = wr * 32 + mi * 16 + (lane >> 2) + half * 8;
                if (bm + rl < M) {
                    atomicAdd(&pbuf[rl * 2 + 0], pacc[mi][half][0]);
                    atomicAdd(&pbuf[rl * 2 + 1], pacc[mi][half][1]);
                }
            }
        __syncthreads();
        if (tid < 128) {
            int r = tid >> 1, c = tid & 1;
            if (bm + r < M) {
                float add = pbuf[tid] +
                            ((blockIdx.x == 0) ? __ldg(&projB[c]) : 0.f);
                atomicAdd(&projOut[(bm + r) * 2 + c], add);
            }
        }
    }
}

// ---------------- pairwise squared distances -------------------------------
__global__ void dist_kernel(const float* __restrict__ proj,
                            const int* __restrict__ idxs,
                            float* __restrict__ out) {
    int i = blockIdx.x * blockDim.x + threadIdx.x;
    if (i >= EE) return;
    int n  = i / (KK - 1);
    int nb = idxs[i];
    float dx = proj[n * 2 + 0] - proj[nb * 2 + 0];
    float dy = proj[n * 2 + 1] - proj[nb * 2 + 1];
    out[i] = dx * dx + dy * dy;
}

// ============================ launch ========================================
extern "C" void kernel_launch(void* const* d_in, const int* in_sizes, int n_in,
                              void* d_out, int out_size) {
    const float* x     = (const float*)d_in[0];
    const float* ea    = (const float*)d_in[1];
    const int*   idxs  = (const int*)  d_in[2];
    const float* l1mw1 = (const float*)d_in[3];   // [785,128]
    const float* l1mb1 = (const float*)d_in[4];
    const float* l1mw2 = (const float*)d_in[5];   // [128,784]
    const float* l1mb2 = (const float*)d_in[6];
    const float* l1nw1 = (const float*)d_in[7];   // [1568,128]
    const float* l1nb1 = (const float*)d_in[8];
    const float* l1nw2 = (const float*)d_in[9];   // [128,128]
    const float* l1nb2 = (const float*)d_in[10];
    const float* l2mw1 = (const float*)d_in[11];  // [129,128]
    const float* l2mb1 = (const float*)d_in[12];
    const float* l2mw2 = (const float*)d_in[13];  // [128,128]
    const float* l2mb2 = (const float*)d_in[14];
    const float* l2nw1 = (const float*)d_in[15];  // [256,128]
    const float* l2nb1 = (const float*)d_in[16];
    const float* l2nw2 = (const float*)d_in[17];  // [128,2]
    const float* l2nb2 = (const float*)d_in[18];
    float* out = (float*)d_out;

    __half *xh, *xl, *Wt1h, *Wf1h, *Wf2h, *Whth, *hbh, *hbl, *hidh, *hidl;
    float *XW, *XW2, *HW2, *proj, *bf1, *bf2, *bh;
    int *csr;
    cudaGetSymbolAddress((void**)&xh,   g_xh);
    cudaGetSymbolAddress((void**)&xl,   g_xl);
    cudaGetSymbolAddress((void**)&Wt1h, g_Wt1h);
    cudaGetSymbolAddress((void**)&Wf1h, g_Wf1h);
    cudaGetSymbolAddress((void**)&Wf2h, g_Wf2h);
    cudaGetSymbolAddress((void**)&Whth, g_Whth);
    cudaGetSymbolAddress((void**)&hbh,  g_hbh);
    cudaGetSymbolAddress((void**)&hbl,  g_hbl);
    cudaGetSymbolAddress((void**)&hidh, g_hidh);
    cudaGetSymbolAddress((void**)&hidl, g_hidl);
    cudaGetSymbolAddress((void**)&XW,   g_XW);
    cudaGetSymbolAddress((void**)&XW2,  g_XW2);
    cudaGetSymbolAddress((void**)&HW2,  g_HW2);
    cudaGetSymbolAddress((void**)&proj, g_proj);
    cudaGetSymbolAddress((void**)&bf1,  g_bf1);
    cudaGetSymbolAddress((void**)&bf2,  g_bf2);
    cudaGetSymbolAddress((void**)&bh,   g_bh);
    cudaGetSymbolAddress((void**)&csr,  g_csr);
    int* cnt = csr;   // first NN entries

    // smem sizes per instantiation
    constexpr int SM_128_2 = 2 * (2 * TILE_A + 128 * TPITCH * 2);  // 40960
    constexpr int SM_64_2  = 2 * (2 * TILE_A + 64 * TPITCH * 2);   // 30720
    cudaFuncSetAttribute((const void*)tgemm<128,2,4>,
                         cudaFuncAttributeMaxDynamicSharedMemorySize, SM_128_2);
    cudaFuncSetAttribute((const void*)tgemm<64,2,3>,
                         cudaFuncAttributeMaxDynamicSharedMemorySize, SM_64_2);

    // ---- memsets: csr state + proj accumulator (atomic fused proj) ----
    cudaMemsetAsync(csr, 0, (2 * NN + 1) * sizeof(int));
    cudaMemsetAsync(proj, 0, NN * 2 * sizeof(float));

    // ---- fold argument pack ----
    FoldArgs fa;
    fa.A[0] = l1mw2;  fa.avec[0] = l1mb2;  fa.B[0] = l1nw1 + (size_t)DD * HH;
    fa.oh[0] = Wf1h;  fa.bf[0] = bf1;
    fa.Kd[0] = DD;    fa.row_off[0] = 0;
    fa.A[1] = l2mw2;  fa.avec[1] = l2mb2;  fa.B[1] = l2nw1 + (size_t)HH * HH;
    fa.oh[1] = Wf2h;  fa.bf[1] = bf2;
    fa.Kd[1] = HH;    fa.row_off[1] = 0;
    fa.A[2] = l1nw2;  fa.avec[2] = l1nb2;  fa.B[2] = l2mw1;
    fa.oh[2] = Whth;  fa.bf[2] = bh;
    fa.Kd[2] = HH;    fa.row_off[2] = 0;
    fa.A[3] = l1nw2;  fa.avec[3] = l1nb2;  fa.B[3] = l2nw1;
    fa.oh[3] = Whth;  fa.bf[3] = bh + 128;
    fa.Kd[3] = HH;    fa.row_off[3] = 128;

    // ---- prep: count + conv + convT + folds in ONE launch ----
    prep_mega<<<PB_TOTAL, 256>>>(idxs, x, l1mw1, l1nw1, xh, xl, Wt1h, fa);
    offs_kernel<<<(NN + 255) / 256, 256>>>();
    fill_kernel<<<(EE + 255) / 256, 256>>>(idxs, ea);

    // ---- layer 1 ----
    // XW (+XW2 split-K) = x @ [W1x_msg | W1a_node]   [N,256]  (K=800, MB=4)
    tgemm<128,2,4><<<dim3(2, 157, 2), 256, SM_128_2>>>(
        xh, xl, KPAD, Wt1h, KPAD, KPAD, NN,
        XW, XW2, 384, 256,
        nullptr, nullptr, nullptr,
        nullptr, nullptr, 0, 0,
        nullptr, nullptr, nullptr, nullptr, nullptr);
    // hbar = mean_e relu((XW+XW2)[:, :128][src] + a*we1 + b1)   (fp16 pair)
    edge_agg<<<(NN * HH + 255) / 256, 256>>>(XW, XW2, 256,
                                             l1mw1 + (size_t)DD * HH,
                                             l1mb1, nullptr, hbh, hbl);
    // hidden1 = relu(hbar@Wf1 + (XW+XW2)[:,128:] + l1nb1 + [cnt>0]*bf1) -> fp16
    tgemm<64,2,3><<<dim3(2, 157, 1), 256, SM_64_2>>>(
        hbh, hbl, HH, Wf1h, HH, HH, NN,
        nullptr, nullptr, 0, 0,
        l1nb1, bf1, cnt,
        XW + 128, XW2 + 128, 256, 1,
        hidh, hidl, nullptr, nullptr, nullptr);

    // ---- layer 2 (intermediate h folded away) ----
    // HW2 = hidden1 @ Wh + bh   [N,256]  BN=64 -> grid (4,157)
    tgemm<64,2,3><<<dim3(4, 157, 1), 256, SM_64_2>>>(
        hidh, hidl, HH, Whth, HH, HH, NN,
        HW2, nullptr, 0, 256,
        bh, nullptr, nullptr,
        nullptr, nullptr, 0, 0,
        nullptr, nullptr, nullptr, nullptr, nullptr);
    // hbar2 = mean_e relu(HW2[:, :128][src] + a*we2 + b1)
    edge_agg<<<(NN * HH + 255) / 256, 256>>>(HW2, nullptr, 256,
                                             l2mw1 + (size_t)HH * HH,
                                             l2mb1, nullptr, hbh, hbl);
    // hidden2 = relu(hbar2@Wf2 + HW2[:,128:] + l2nb1 + [cnt>0]*bf2) -> fused
    // proj via global atomicAdd (proj pre-zeroed); BN=64 -> grid (2,157)
    tgemm<64,2,3><<<dim3(2, 157, 1), 256, SM_64_2>>>(
        hbh, hbl, HH, Wf2h, HH, HH, NN,
        nullptr, nullptr, 0, 0,
        l2nb1, bf2, cnt,
        HW2 + 128, nullptr, 256, 1,
        nullptr, nullptr, l2nw2, l2nb2, proj);

    // ---- output ----
    dist_kernel<<<(EE + 255) / 256, 256>>>(proj, idxs, out);
}

// round 15
// speedup vs baseline: 1.0020x; 1.0020x over previous
#include <cuda_runtime.h>
#include <cuda_fp16.h>
#include <cstdint>

// Problem constants (fixed by the reference)
#define NN 10000          // nodes
#define DD 784            // input feat dim
#define KPAD 800          // DD padded to multiple of 32 (pad cols stay zero)
#define KK 16             // neighbors+1
#define EE (NN * (KK-1))  // edges = 150000
#define HH 128            // hidden width

// ============================ scratch globals ===============================
// Numeric scheme (FROZEN since R12): A-side exact via fp16 hi/lo pair;
// B-side (weights) single fp16. GEMM computes (Ah+Al)@Bh -> 2 MMA products.
__device__ __align__(256) __half g_xh   [NN * KPAD];
__device__ __align__(256) __half g_xl   [NN * KPAD];
__device__ __align__(256) __half g_Wt1h [256 * KPAD]; // [l1 msgW1x^T ; l1 nodeW1a^T]
__device__ __align__(256) __half g_Wf1h [HH * HH];    // (l1 msgW2 @ l1 nodeW1b)^T
__device__ __align__(256) __half g_Wf2h [HH * HH];
__device__ __align__(256) __half g_Whth [256 * HH];   // (l1 nodeW2 @ [l2 W1x | l2 W1a])^T
__device__ __align__(256) float g_bf1[HH];
__device__ __align__(256) float g_bf2[HH];
__device__ __align__(256) float g_bh [256];
__device__ __align__(256) float g_XW  [NN * 256];   // split-K part 0
__device__ __align__(256) float g_XW2 [NN * 256];   // split-K part 1
__device__ __align__(256) float g_HW2 [NN * 256];
__device__ __align__(256) __half g_hbh [NN * HH];     // hbar hi/lo
__device__ __align__(256) __half g_hbl [NN * HH];
__device__ __align__(256) __half g_hidh[NN * HH];     // hidden hi/lo
__device__ __align__(256) __half g_hidl[NN * HH];
__device__ __align__(256) float g_proj[NN * 2];
__device__ int   g_csr [2 * NN + 1];   // [cnt | pos | counter] -> ONE memset
__device__ int   g_offs[NN];
__device__ __align__(256) float g_bucket[EE];

// ============================ prep megakernel ===============================
struct FoldArgs {
    const float* A[4];
    const float* avec[4];
    const float* B[4];
    __half* oh[4];
    float* bf[4];
    int Kd[4];
    int row_off[4];
};

#define PB_COUNT 586
#define PB_CONV  7657
#define PB_CONVT 1024     // 2 weights x (4 k-blocks x 128 n)
#define PB_FOLD  516      // 4 folds x 129 rows
#define PB_TOTAL (PB_COUNT + PB_CONV + PB_CONVT + PB_FOLD)

__global__ void __launch_bounds__(256)
prep_mega(const int* __restrict__ idxs, const float* __restrict__ x,
          const float* __restrict__ Wc0, const float* __restrict__ Wc1,
          __half* __restrict__ xh, __half* __restrict__ xl,
          __half* __restrict__ Wt1h, FoldArgs fa) {
    __shared__ float red[256];
    int b = blockIdx.x, tid = threadIdx.x;

    if (b < PB_COUNT) {                       // ---- edge count ----
        int e = b * 256 + tid;
        if (e < EE) atomicAdd(&g_csr[idxs[e]], 1);
        return;
    }
    b -= PB_COUNT;
    if (b < PB_CONV) {                        // ---- x fp16 hi/lo split ----
        int i = b * 256 + tid;
        if (i >= NN * (DD / 4)) return;
        int row = i / (DD / 4), c = i % (DD / 4);
        float4 v = ((const float4*)(x + (size_t)row * DD))[c];
        __half h0 = __float2half(v.x), h1 = __float2half(v.y);
        __half h2 = __float2half(v.z), h3 = __float2half(v.w);
        __half l0 = __float2half(v.x - __half2float(h0));
        __half l1 = __float2half(v.y - __half2float(h1));
        __half l2 = __float2half(v.z - __half2float(h2));
        __half l3 = __float2half(v.w - __half2float(h3));
        size_t o = (size_t)row * KPAD + c * 4;
        *(__half2*)(xh + o)     = __half2(h0, h1);
        *(__half2*)(xh + o + 2) = __half2(h2, h3);
        *(__half2*)(xl + o)     = __half2(l0, l1);
        *(__half2*)(xl + o + 2) = __half2(l2, l3);
        return;
    }
    b -= PB_CONV;
    if (b < PB_CONVT) {                       // ---- W1 transpose, fp16 hi ----
        int z = b >> 9;                       // which weight (0/1)
        int rem = b & 511;
        int kb = rem & 3, n = rem >> 2;
        int k = kb * 256 + tid;
        if (k >= DD) return;
        const float* W = z ? Wc1 : Wc0;
        float v = W[(size_t)k * 128 + n];
        Wt1h[(size_t)(z * 128 + n) * KPAD + k] = __float2half(v);
        return;
    }
    b -= PB_CONVT;
    {                                         // ---- weight folds (fp16 hi) ----
        int f = b / 129, i = b % 129;
        int j = tid & 127, kq = tid >> 7;     // 2-way K split
        int Kd = fa.Kd[f];
        const float* arow = (i < 128) ? (fa.A[f] + (size_t)i * Kd) : fa.avec[f];
        const float* B = fa.B[f];
        int chunk = (Kd + 1) >> 1;
        int k0 = kq * chunk, k1 = min(Kd, k0 + chunk);
        float s = 0.f;
        #pragma unroll 4
        for (int k = k0; k < k1; k++)
            s = fmaf(__ldg(&arow[k]), B[(size_t)k * HH + j], s);
        red[tid] = s;
        __syncthreads();
        if (kq == 0) {
            s = red[j] + red[128 + j];
            if (i < 128)
                fa.oh[f][(size_t)(fa.row_off[f] + j) * HH + i] = __float2half(s);
            else
                fa.bf[f][j] = s;
        }
        return;
    }
}

// offsets need only be disjoint ranges, not ordered -> block scan + atomic base
__global__ void offs_kernel() {
    __shared__ int sd[256];
    __shared__ int base_s;
    int t = threadIdx.x;
    int i = blockIdx.x * 256 + t;
    int v = (i < NN) ? g_csr[i] : 0;
    sd[t] = v;
    __syncthreads();
    #pragma unroll
    for (int o = 1; o < 256; o <<= 1) {
        int x = (t >= o) ? sd[t - o] : 0;
        __syncthreads();
        sd[t] += x;
        __syncthreads();
    }
    if (t == 255) base_s = atomicAdd(&g_csr[2 * NN], sd[255]);
    __syncthreads();
    if (i < NN) g_offs[i] = base_s + sd[t] - v;
}

__global__ void fill_kernel(const int* __restrict__ idxs,
                            const float* __restrict__ ea) {
    int e = blockIdx.x * blockDim.x + threadIdx.x;
    if (e < EE) {
        int s = idxs[e];
        int p = atomicAdd(&g_csr[NN + s], 1);
        g_bucket[g_offs[s] + p] = ea[e];
    }
}

// flat per-(node,col) edge aggregation; optional second split-K buffer:
// hbar[m,j] = mean_e relu(xwA[m,j] (+ xwB[m,j]) + b[j] (+ b2[j]) + a_e*we[j])
__global__ void edge_agg(const float* __restrict__ xwA,
                         const float* __restrict__ xwB, int ld,
                         const float* __restrict__ we,
                         const float* __restrict__ b,
                         const float* __restrict__ b2,
                         __half* __restrict__ oh,
                         __half* __restrict__ ol) {
    int idx = blockIdx.x * blockDim.x + threadIdx.x;
    if (idx >= NN * HH) return;
    int m = idx >> 7;
    int j = idx & 127;
    int deg = g_csr[m];
    int start = g_offs[m];
    float xj = xwA[(size_t)m * ld + j] + __ldg(&b[j]);
    if (xwB) xj += xwB[(size_t)m * ld + j];
    if (b2)  xj += __ldg(&b2[j]);
    float wj = __ldg(&we[j]);
    float s = 0.f;
    for (int t = 0; t < deg; t++)
        s += fmaxf(fmaf(g_bucket[start + t], wj, xj), 0.f);
    float v = deg ? s / (float)deg : 0.f;
    __half h = __float2half(v);
    oh[(size_t)m * HH + j] = h;
    ol[(size_t)m * HH + j] = __float2half(v - __half2float(h));
}

// ============================ mma.sync GEMM ================================
// C[M,Ntot] = (Ah+Al)[M,K] @ Bh^T (B stored [Ntot][K] fp16); 2-product.
// Block tile 64xBN, BK=32, 8 warps (2 M x 4 N), STAGES-deep cp.async pipeline,
// MB min-blocks occupancy bound. Optional split-K via gridDim.z==2.
// Fused projection (projOut != nullptr) accumulates partial row-projections
// via global atomicAdd (projOut must be pre-zeroed; projB added by block x==0).
#define TPITCH 40                      // fp16 pitch (80 B) per smem tile row
#define TILE_A (64 * TPITCH * 2)       // 5120 B

__device__ __forceinline__ uint32_t smem_u32(const void* p) {
    uint32_t a;
    asm("{ .reg .u64 t; cvta.to.shared.u64 t, %1; cvt.u32.u64 %0, t; }"
        : "=r"(a) : "l"(p));
    return a;
}
__device__ __forceinline__ void cp16(uint32_t dst, const void* src, int sz) {
    asm volatile("cp.async.cg.shared.global [%0], [%1], 16, %2;"
        :: "r"(dst), "l"(src), "r"(sz) : "memory");
}
__device__ __forceinline__ void ldsm_x4(uint32_t* r, uint32_t a) {
    asm volatile("ldmatrix.sync.aligned.m8n8.x4.shared.b16 {%0,%1,%2,%3}, [%4];"
        : "=r"(r[0]), "=r"(r[1]), "=r"(r[2]), "=r"(r[3]) : "r"(a));
}
__device__ __forceinline__ void mma_f16(float* c, const uint32_t* a, const uint32_t* b) {
    asm volatile("mma.sync.aligned.m16n8k16.row.col.f32.f16.f16.f32 "
        "{%0,%1,%2,%3}, {%4,%5,%6,%7}, {%8,%9}, {%0,%1,%2,%3};"
        : "+f"(c[0]), "+f"(c[1]), "+f"(c[2]), "+f"(c[3])
        : "r"(a[0]), "r"(a[1]), "r"(a[2]), "r"(a[3]), "r"(b[0]), "r"(b[1]));
}

template<int BN, int STAGES, int MB>
__global__ void __launch_bounds__(256, MB)
tgemm(const __half* __restrict__ Ah, const __half* __restrict__ Al,
      int lda,
      const __half* __restrict__ Bh, int ldb, int K, int M,
      float* __restrict__ C, float* __restrict__ C2, int ksplit, int ldc,
      const float* __restrict__ bias,
      const float* __restrict__ cbias, const int* __restrict__ cnt,
      const float* __restrict__ addend, const float* __restrict__ addend2,
      int addld, int relu,
      __half* __restrict__ outHi, __half* __restrict__ outLo,
      const float* __restrict__ projW, const float* __restrict__ projB,
      float* __restrict__ projOut) {
    constexpr int TILE_Bn = BN * TPITCH * 2;
    constexpr int STG_B = 2 * TILE_A + TILE_Bn;
    constexpr int NI = BN / 32;        // fragment column groups
    constexpr int NP = NI / 2;         // ldsm_x4 B loads per ks
    constexpr int WCW = BN / 4;        // cols per N-warp
    constexpr int NCH = 512 + BN * 4;  // 16B chunks per stage
    constexpr int U = NCH / 256;

    extern __shared__ char smem[];
    uint32_t sb = smem_u32(smem);
    int tid = threadIdx.x;
    int wid = tid >> 5, lane = tid & 31;
    int bm = blockIdx.y * 64;
    int bn = blockIdx.x * BN;
    int wr = wid & 1;        // M warp (0..1), 32 rows each
    int wc = wid >> 1;       // N warp (0..3), WCW cols each

    // split-K resolution
    int kb = 0, ke = K;
    float* Cw = C;
    if (gridDim.z == 2) {
        if (blockIdx.z == 1) { kb = ksplit; Cw = C2; }
        else                 { ke = ksplit; }
    }
    const __half* srcs[3] = {Ah + kb, Al + kb, Bh + kb};
    const int toff[3] = {0, TILE_A, 2 * TILE_A};

    auto issue = [&](int kc, int stg) {
        int k0 = kc * 32;
        #pragma unroll
        for (int u = 0; u < U; u++) {
            int idx = tid + u * 256;
            int tile, row;
            if (idx < 256)      { tile = 0; row = idx >> 2; }
            else if (idx < 512) { tile = 1; row = (idx - 256) >> 2; }
            else                { tile = 2; row = (idx - 512) >> 2; }
            int c = idx & 3;
            int gr, maxr;
            if (tile < 2) { gr = bm + row; maxr = M; }
            else          { gr = bn + row; maxr = 1 << 30; }
            const __half* s = srcs[tile] +
                (size_t)gr * ((tile < 2) ? lda : ldb) + k0 + c * 8;
            uint32_t d = sb + stg * STG_B + toff[tile] + row * (TPITCH * 2) + c * 16;
            cp16(d, s, (gr < maxr) ? 16 : 0);
        }
        asm volatile("cp.async.commit_group;" ::: "memory");
    };

    float acc[2][NI][4] = {};
    int nT = (ke - kb) / 32;

    issue(0, 0);
    for (int t = 0; t < nT; t++) {
        int stg = t % STAGES;
        if (t + 1 < nT) {
            issue(t + 1, (t + 1) % STAGES);
            asm volatile("cp.async.wait_group 1;" ::: "memory");
        } else {
            asm volatile("cp.async.wait_group 0;" ::: "memory");
        }
        __syncthreads();

        uint32_t baseAH = sb + stg * STG_B + toff[0];
        uint32_t baseAL = sb + stg * STG_B + toff[1];
        uint32_t baseBH = sb + stg * STG_B + toff[2];

        #pragma unroll
        for (int ks = 0; ks < 2; ks++) {
            uint32_t aH[2][4], aL[2][4], bH[NP][4];
            int acol = (ks * 16 + (lane >> 4) * 8) * 2;
            int bcol = (ks * 16 + ((lane >> 3) & 1) * 8) * 2;
            #pragma unroll
            for (int mi = 0; mi < 2; mi++) {
                int arow = wr * 32 + mi * 16 + (lane & 15);
                ldsm_x4(aH[mi], baseAH + arow * (TPITCH * 2) + acol);
                ldsm_x4(aL[mi], baseAL + arow * (TPITCH * 2) + acol);
            }
            #pragma unroll
            for (int np = 0; np < NP; np++) {
                int brow = wc * WCW + np * 16 + ((lane >> 4) & 1) * 8 + (lane & 7);
                ldsm_x4(bH[np], baseBH + brow * (TPITCH * 2) + bcol);
            }
            #pragma unroll
            for (int mi = 0; mi < 2; mi++)
                #pragma unroll
                for (int ni = 0; ni < NI; ni++) {
                    const uint32_t* bh_ = &bH[ni >> 1][(ni & 1) * 2];
                    mma_f16(acc[mi][ni], aH[mi], bh_);
                    mma_f16(acc[mi][ni], aL[mi], bh_);
                }
        }
        __syncthreads();
    }

    // ---- epilogue ----
    float* pbuf = (float*)smem;               // 64 rows x 2 proj accumulators
    if (projOut) {
        for (int i = tid; i < 128; i += 256) pbuf[i] = 0.f;
        __syncthreads();
    }
    float pacc[2][2][2] = {};
    #pragma unroll
    for (int mi = 0; mi < 2; mi++) {
        #pragma unroll
        for (int half = 0; half < 2; half++) {
            int gm = bm + wr * 32 + mi * 16 + (lane >> 2) + half * 8;
            if (gm >= M) continue;
            bool cb = (cbias != nullptr) && (cnt[gm] > 0);
            #pragma unroll
            for (int ni = 0; ni < NI; ni++) {
                #pragma unroll
                for (int e = 0; e < 2; e++) {
                    int gn = bn + wc * WCW + ni * 8 + (lane & 3) * 2 + e;
                    float v = acc[mi][ni][half * 2 + e];
                    if (bias)    v += __ldg(&bias[gn]);
                    if (cb)      v += __ldg(&cbias[gn]);
                    if (addend)  v += addend[(size_t)gm * addld + gn];
                    if (addend2) v += addend2[(size_t)gm * addld + gn];
                    if (relu)    v = fmaxf(v, 0.f);
                    if (Cw) Cw[(size_t)gm * ldc + gn] = v;
                    if (outHi) {
                        __half h = __float2half(v);
                        outHi[(size_t)gm * 128 + gn] = h;
                        outLo[(size_t)gm * 128 + gn] =
                            __float2half(v - __half2float(h));
                    }
                    if (projOut) {
                        pacc[mi][half][0] = fmaf(v, __ldg(&projW[gn * 2 + 0]),
                                                 pacc[mi][half][0]);
                        pacc[mi][half][1] = fmaf(v, __ldg(&projW[gn * 2 + 1]),
                                                 pacc[mi][half][1]);
                    }
                }
            }
        }
    }
    if (projOut) {
        #pragma unroll
        for (int mi = 0; mi < 2; mi++)
            #pragma unroll
            for (int half = 0; half < 2; half++) {
                int rl = wr * 32 + mi * 16 + (lane >> 2) + half * 8;
                if (bm + rl < M) {
                    atomicAdd(&pbuf[rl * 2 + 0], pacc[mi][half][0]);
                    atomicAdd(&pbuf[rl * 2 + 1], pacc[mi][half][1]);
                }
            }
        __syncthreads();
        if (tid < 128) {
            int r = tid >> 1, c = tid & 1;
            if (bm + r < M) {
                float add = pbuf[tid] +
                            ((blockIdx.x == 0) ? __ldg(&projB[c]) : 0.f);
                atomicAdd(&projOut[(bm + r) * 2 + c], add);
            }
        }
    }
}

// ---------------- pairwise squared distances -------------------------------
__global__ void dist_kernel(const float* __restrict__ proj,
                            const int* __restrict__ idxs,
                            float* __restrict__ out) {
    int i = blockIdx.x * blockDim.x + threadIdx.x;
    if (i >= EE) return;
    int n  = i / (KK - 1);
    int nb = idxs[i];
    float dx = proj[n * 2 + 0] - proj[nb * 2 + 0];
    float dy = proj[n * 2 + 1] - proj[nb * 2 + 1];
    out[i] = dx * dx + dy * dy;
}

// ============================ launch ========================================
extern "C" void kernel_launch(void* const* d_in, const int* in_sizes, int n_in,
                              void* d_out, int out_size) {
    const float* x     = (const float*)d_in[0];
    const float* ea    = (const float*)d_in[1];
    const int*   idxs  = (const int*)  d_in[2];
    const float* l1mw1 = (const float*)d_in[3];   // [785,128]
    const float* l1mb1 = (const float*)d_in[4];
    const float* l1mw2 = (const float*)d_in[5];   // [128,784]
    const float* l1mb2 = (const float*)d_in[6];
    const float* l1nw1 = (const float*)d_in[7];   // [1568,128]
    const float* l1nb1 = (const float*)d_in[8];
    const float* l1nw2 = (const float*)d_in[9];   // [128,128]
    const float* l1nb2 = (const float*)d_in[10];
    const float* l2mw1 = (const float*)d_in[11];  // [129,128]
    const float* l2mb1 = (const float*)d_in[12];
    const float* l2mw2 = (const float*)d_in[13];  // [128,128]
    const float* l2mb2 = (const float*)d_in[14];
    const float* l2nw1 = (const float*)d_in[15];  // [256,128]
    const float* l2nb1 = (const float*)d_in[16];
    const float* l2nw2 = (const float*)d_in[17];  // [128,2]
    const float* l2nb2 = (const float*)d_in[18];
    float* out = (float*)d_out;

    __half *xh, *xl, *Wt1h, *Wf1h, *Wf2h, *Whth, *hbh, *hbl, *hidh, *hidl;
    float *XW, *XW2, *HW2, *proj, *bf1, *bf2, *bh;
    int *csr;
    cudaGetSymbolAddress((void**)&xh,   g_xh);
    cudaGetSymbolAddress((void**)&xl,   g_xl);
    cudaGetSymbolAddress((void**)&Wt1h, g_Wt1h);
    cudaGetSymbolAddress((void**)&Wf1h, g_Wf1h);
    cudaGetSymbolAddress((void**)&Wf2h, g_Wf2h);
    cudaGetSymbolAddress((void**)&Whth, g_Whth);
    cudaGetSymbolAddress((void**)&hbh,  g_hbh);
    cudaGetSymbolAddress((void**)&hbl,  g_hbl);
    cudaGetSymbolAddress((void**)&hidh, g_hidh);
    cudaGetSymbolAddress((void**)&hidl, g_hidl);
    cudaGetSymbolAddress((void**)&XW,   g_XW);
    cudaGetSymbolAddress((void**)&XW2,  g_XW2);
    cudaGetSymbolAddress((void**)&HW2,  g_HW2);
    cudaGetSymbolAddress((void**)&proj, g_proj);
    cudaGetSymbolAddress((void**)&bf1,  g_bf1);
    cudaGetSymbolAddress((void**)&bf2,  g_bf2);
    cudaGetSymbolAddress((void**)&bh,   g_bh);
    cudaGetSymbolAddress((void**)&csr,  g_csr);
    int* cnt = csr;   // first NN entries

    // smem sizes per instantiation
    constexpr int SM_128_2 = 2 * (2 * TILE_A + 128 * TPITCH * 2);  // 40960
    constexpr int SM_64_2  = 2 * (2 * TILE_A + 64 * TPITCH * 2);   // 30720
    cudaFuncSetAttribute((const void*)tgemm<128,2,3>,
                         cudaFuncAttributeMaxDynamicSharedMemorySize, SM_128_2);
    cudaFuncSetAttribute((const void*)tgemm<64,2,3>,
                         cudaFuncAttributeMaxDynamicSharedMemorySize, SM_64_2);

    // ---- memsets: csr state + proj accumulator (atomic fused proj) ----
    cudaMemsetAsync(csr, 0, (2 * NN + 1) * sizeof(int));
    cudaMemsetAsync(proj, 0, NN * 2 * sizeof(float));

    // ---- fold argument pack ----
    FoldArgs fa;
    fa.A[0] = l1mw2;  fa.avec[0] = l1mb2;  fa.B[0] = l1nw1 + (size_t)DD * HH;
    fa.oh[0] = Wf1h;  fa.bf[0] = bf1;
    fa.Kd[0] = DD;    fa.row_off[0] = 0;
    fa.A[1] = l2mw2;  fa.avec[1] = l2mb2;  fa.B[1] = l2nw1 + (size_t)HH * HH;
    fa.oh[1] = Wf2h;  fa.bf[1] = bf2;
    fa.Kd[1] = HH;    fa.row_off[1] = 0;
    fa.A[2] = l1nw2;  fa.avec[2] = l1nb2;  fa.B[2] = l2mw1;
    fa.oh[2] = Whth;  fa.bf[2] = bh;
    fa.Kd[2] = HH;    fa.row_off[2] = 0;
    fa.A[3] = l1nw2;  fa.avec[3] = l1nb2;  fa.B[3] = l2nw1;
    fa.oh[3] = Whth;  fa.bf[3] = bh + 128;
    fa.Kd[3] = HH;    fa.row_off[3] = 128;

    // ---- prep: count + conv + convT + folds in ONE launch ----
    prep_mega<<<PB_TOTAL, 256>>>(idxs, x, l1mw1, l1nw1, xh, xl, Wt1h, fa);
    offs_kernel<<<(NN + 255) / 256, 256>>>();
    fill_kernel<<<(EE + 255) / 256, 256>>>(idxs, ea);

    // ---- layer 1 ----
    // XW (+XW2 split-K) = x @ [W1x_msg | W1a_node]   [N,256]
    // (K=800; MB=3 / regs=80 -- measured best; MB=4 regressed in R14)
    tgemm<128,2,3><<<dim3(2, 157, 2), 256, SM_128_2>>>(
        xh, xl, KPAD, Wt1h, KPAD, KPAD, NN,
        XW, XW2, 384, 256,
        nullptr, nullptr, nullptr,
        nullptr, nullptr, 0, 0,
        nullptr, nullptr, nullptr, nullptr, nullptr);
    // hbar = mean_e relu((XW+XW2)[:, :128][src] + a*we1 + b1)   (fp16 pair)
    edge_agg<<<(NN * HH + 255) / 256, 256>>>(XW, XW2, 256,
                                             l1mw1 + (size_t)DD * HH,
                                             l1mb1, nullptr, hbh, hbl);
    // hidden1 = relu(hbar@Wf1 + (XW+XW2)[:,128:] + l1nb1 + [cnt>0]*bf1) -> fp16
    tgemm<64,2,3><<<dim3(2, 157, 1), 256, SM_64_2>>>(
        hbh, hbl, HH, Wf1h, HH, HH, NN,
        nullptr, nullptr, 0, 0,
        l1nb1, bf1, cnt,
        XW + 128, XW2 + 128, 256, 1,
        hidh, hidl, nullptr, nullptr, nullptr);

    // ---- layer 2 (intermediate h folded away) ----
    // HW2 = hidden1 @ Wh + bh   [N,256]  BN=64 -> grid (4,157)
    tgemm<64,2,3><<<dim3(4, 157, 1), 256, SM_64_2>>>(
        hidh, hidl, HH, Whth, HH, HH, NN,
        HW2, nullptr, 0, 256,
        bh, nullptr, nullptr,
        nullptr, nullptr, 0, 0,
        nullptr, nullptr, nullptr, nullptr, nullptr);
    // hbar2 = mean_e relu(HW2[:, :128][src] + a*we2 + b1)
    edge_agg<<<(NN * HH + 255) / 256, 256>>>(HW2, nullptr, 256,
                                             l2mw1 + (size_t)HH * HH,
                                             l2mb1, nullptr, hbh, hbl);
    // hidden2 = relu(hbar2@Wf2 + HW2[:,128:] + l2nb1 + [cnt>0]*bf2) -> fused
    // proj via global atomicAdd (proj pre-zeroed); BN=64 -> grid (2,157)
    tgemm<64,2,3><<<dim3(2, 157, 1), 256, SM_64_2>>>(
        hbh, hbl, HH, Wf2h, HH, HH, NN,
        nullptr, nullptr, 0, 0,
        l2nb1, bf2, cnt,
        HW2 + 128, nullptr, 256, 1,
        nullptr, nullptr, l2nw2, l2nb2, proj);

    // ---- output ----
    dist_kernel<<<(EE + 255) / 256, 256>>>(proj, idxs, out);
}

// round 16
// speedup vs baseline: 1.0343x; 1.0322x over previous
#include <cuda_runtime.h>
#include <cuda_fp16.h>
#include <cstdint>

// Problem constants (fixed by the reference)
#define NN 10000          // nodes
#define DD 784            // input feat dim
#define KPAD 800          // DD padded to multiple of 32 (pad cols stay zero)
#define KK 16             // neighbors+1
#define EE (NN * (KK-1))  // edges = 150000
#define HH 128            // hidden width
#define CAP 96            // fixed bucket capacity per node (P(deg>=96) ~ 0)

// ============================ scratch globals ===============================
// Numeric scheme (FROZEN since R12): A-side exact via fp16 hi/lo pair;
// B-side (weights) single fp16. GEMM computes (Ah+Al)@Bh -> 2 MMA products.
__device__ __align__(256) __half g_xh   [NN * KPAD];
__device__ __align__(256) __half g_xl   [NN * KPAD];
__device__ __align__(256) __half g_Wt1h [256 * KPAD]; // [l1 msgW1x^T ; l1 nodeW1a^T]
__device__ __align__(256) __half g_Wf1h [HH * HH];    // (l1 msgW2 @ l1 nodeW1b)^T
__device__ __align__(256) __half g_Wf2h [HH * HH];
__device__ __align__(256) __half g_Whth [256 * HH];   // (l1 nodeW2 @ [l2 W1x | l2 W1a])^T
__device__ __align__(256) float g_bf1[HH];
__device__ __align__(256) float g_bf2[HH];
__device__ __align__(256) float g_bh [256];
__device__ __align__(256) float g_XW  [NN * 256];   // split-K part 0
__device__ __align__(256) float g_XW2 [NN * 256];   // split-K part 1
__device__ __align__(256) float g_HW2 [NN * 256];
__device__ __align__(256) __half g_hbh [NN * HH];     // hbar hi/lo
__device__ __align__(256) __half g_hbl [NN * HH];
__device__ __align__(256) __half g_hidh[NN * HH];     // hidden hi/lo
__device__ __align__(256) __half g_hidl[NN * HH];
__device__ __align__(256) float g_proj[NN * 2];
__device__ int   g_pos [NN];            // degree counters (also the cnt array)
__device__ __align__(256) float g_bucket[NN * CAP];   // fixed-stride edge lists

// ============================ prep megakernel ===============================
struct FoldArgs {
    const float* A[4];
    const float* avec[4];
    const float* B[4];
    __half* oh[4];
    float* bf[4];
    int Kd[4];
    int row_off[4];
};

#define PB_CONV  7657
#define PB_CONVT 1024     // 2 weights x (4 k-blocks x 128 n)
#define PB_FOLD  516      // 4 folds x 129 rows
#define PB_TOTAL (PB_CONV + PB_CONVT + PB_FOLD)

__global__ void __launch_bounds__(256)
prep_mega(const float* __restrict__ x,
          const float* __restrict__ Wc0, const float* __restrict__ Wc1,
          __half* __restrict__ xh, __half* __restrict__ xl,
          __half* __restrict__ Wt1h, FoldArgs fa) {
    __shared__ float red[256];
    int b = blockIdx.x, tid = threadIdx.x;

    if (b < PB_CONV) {                        // ---- x fp16 hi/lo split ----
        int i = b * 256 + tid;
        if (i >= NN * (DD / 4)) return;
        int row = i / (DD / 4), c = i % (DD / 4);
        float4 v = ((const float4*)(x + (size_t)row * DD))[c];
        __half h0 = __float2half(v.x), h1 = __float2half(v.y);
        __half h2 = __float2half(v.z), h3 = __float2half(v.w);
        __half l0 = __float2half(v.x - __half2float(h0));
        __half l1 = __float2half(v.y - __half2float(h1));
        __half l2 = __float2half(v.z - __half2float(h2));
        __half l3 = __float2half(v.w - __half2float(h3));
        size_t o = (size_t)row * KPAD + c * 4;
        *(__half2*)(xh + o)     = __half2(h0, h1);
        *(__half2*)(xh + o + 2) = __half2(h2, h3);
        *(__half2*)(xl + o)     = __half2(l0, l1);
        *(__half2*)(xl + o + 2) = __half2(l2, l3);
        return;
    }
    b -= PB_CONV;
    if (b < PB_CONVT) {                       // ---- W1 transpose, fp16 hi ----
        int z = b >> 9;                       // which weight (0/1)
        int rem = b & 511;
        int kb = rem & 3, n = rem >> 2;
        int k = kb * 256 + tid;
        if (k >= DD) return;
        const float* W = z ? Wc1 : Wc0;
        float v = W[(size_t)k * 128 + n];
        Wt1h[(size_t)(z * 128 + n) * KPAD + k] = __float2half(v);
        return;
    }
    b -= PB_CONVT;
    {                                         // ---- weight folds (fp16 hi) ----
        int f = b / 129, i = b % 129;
        int j = tid & 127, kq = tid >> 7;     // 2-way K split
        int Kd = fa.Kd[f];
        const float* arow = (i < 128) ? (fa.A[f] + (size_t)i * Kd) : fa.avec[f];
        const float* B = fa.B[f];
        int chunk = (Kd + 1) >> 1;
        int k0 = kq * chunk, k1 = min(Kd, k0 + chunk);
        float s = 0.f;
        #pragma unroll 4
        for (int k = k0; k < k1; k++)
            s = fmaf(__ldg(&arow[k]), B[(size_t)k * HH + j], s);
        red[tid] = s;
        __syncthreads();
        if (kq == 0) {
            s = red[j] + red[128 + j];
            if (i < 128)
                fa.oh[f][(size_t)(fa.row_off[f] + j) * HH + i] = __float2half(s);
            else
                fa.bf[f][j] = s;
        }
        return;
    }
}

// fixed-stride bucket fill: pos doubles as the degree/cnt array
__global__ void fill_kernel(const int* __restrict__ idxs,
                            const float* __restrict__ ea) {
    int e = blockIdx.x * blockDim.x + threadIdx.x;
    if (e < EE) {
        int s = idxs[e];
        int p = atomicAdd(&g_pos[s], 1);
        if (p < CAP) g_bucket[s * CAP + p] = ea[e];
    }
}

// flat per-(node,col) edge aggregation; optional second split-K buffer:
// hbar[m,j] = mean_e relu(xwA[m,j] (+ xwB[m,j]) + b[j] + a_e*we[j])
__global__ void edge_agg(const float* __restrict__ xwA,
                         const float* __restrict__ xwB, int ld,
                         const float* __restrict__ we,
                         const float* __restrict__ b,
                         __half* __restrict__ oh,
                         __half* __restrict__ ol) {
    int idx = blockIdx.x * blockDim.x + threadIdx.x;
    if (idx >= NN * HH) return;
    int m = idx >> 7;
    int j = idx & 127;
    int deg = min(g_pos[m], CAP);
    int start = m * CAP;
    float xj = xwA[(size_t)m * ld + j] + __ldg(&b[j]);
    if (xwB) xj += xwB[(size_t)m * ld + j];
    float wj = __ldg(&we[j]);
    float s = 0.f;
    for (int t = 0; t < deg; t++)
        s += fmaxf(fmaf(g_bucket[start + t], wj, xj), 0.f);
    float v = deg ? s / (float)deg : 0.f;
    __half h = __float2half(v);
    oh[(size_t)m * HH + j] = h;
    ol[(size_t)m * HH + j] = __float2half(v - __half2float(h));
}

// ============================ mma.sync GEMM ================================
// C[M,Ntot] = (Ah+Al)[M,K] @ Bh^T (B stored [Ntot][K] fp16); 2-product.
// Block tile 64xBN, BK=32, 8 warps (2 M x 4 N), STAGES-deep cp.async pipeline,
// MB min-blocks occupancy bound. Optional split-K via gridDim.z==2.
// Fused projection (projOut != nullptr) accumulates partial row-projections
// via global atomicAdd (projOut must be pre-zeroed; projB added by block x==0).
#define TPITCH 40                      // fp16 pitch (80 B) per smem tile row
#define TILE_A (64 * TPITCH * 2)       // 5120 B

__device__ __forceinline__ uint32_t smem_u32(const void* p) {
    uint32_t a;
    asm("{ .reg .u64 t; cvta.to.shared.u64 t, %1; cvt.u32.u64 %0, t; }"
        : "=r"(a) : "l"(p));
    return a;
}
__device__ __forceinline__ void cp16(uint32_t dst, const void* src, int sz) {
    asm volatile("cp.async.cg.shared.global [%0], [%1], 16, %2;"
        :: "r"(dst), "l"(src), "r"(sz) : "memory");
}
__device__ __forceinline__ void ldsm_x4(uint32_t* r, uint32_t a) {
    asm volatile("ldmatrix.sync.aligned.m8n8.x4.shared.b16 {%0,%1,%2,%3}, [%4];"
        : "=r"(r[0]), "=r"(r[1]), "=r"(r[2]), "=r"(r[3]) : "r"(a));
}
__device__ __forceinline__ void mma_f16(float* c, const uint32_t* a, const uint32_t* b) {
    asm volatile("mma.sync.aligned.m16n8k16.row.col.f32.f16.f16.f32 "
        "{%0,%1,%2,%3}, {%4,%5,%6,%7}, {%8,%9}, {%0,%1,%2,%3};"
        : "+f"(c[0]), "+f"(c[1]), "+f"(c[2]), "+f"(c[3])
        : "r"(a[0]), "r"(a[1]), "r"(a[2]), "r"(a[3]), "r"(b[0]), "r"(b[1]));
}

template<int BN, int STAGES, int MB>
__global__ void __launch_bounds__(256, MB)
tgemm(const __half* __restrict__ Ah, const __half* __restrict__ Al,
      int lda,
      const __half* __restrict__ Bh, int ldb, int K, int M,
      float* __restrict__ C, float* __restrict__ C2, int ksplit, int ldc,
      const float* __restrict__ bias,
      const float* __restrict__ cbias, const int* __restrict__ cnt,
      const float* __restrict__ addend, const float* __restrict__ addend2,
      int addld, int relu,
      __half* __restrict__ outHi, __half* __restrict__ outLo,
      const float* __restrict__ projW, const float* __restrict__ projB,
      float* __restrict__ projOut) {
    constexpr int TILE_Bn = BN * TPITCH * 2;
    constexpr int STG_B = 2 * TILE_A + TILE_Bn;
    constexpr int NI = BN / 32;        // fragment column groups
    constexpr int NP = NI / 2;         // ldsm_x4 B loads per ks
    constexpr int WCW = BN / 4;        // cols per N-warp
    constexpr int NCH = 512 + BN * 4;  // 16B chunks per stage
    constexpr int U = NCH / 256;

    extern __shared__ char smem[];
    uint32_t sb = smem_u32(smem);
    int tid = threadIdx.x;
    int wid = tid >> 5, lane = tid & 31;
    int bm = blockIdx.y * 64;
    int bn = blockIdx.x * BN;
    int wr = wid & 1;        // M warp (0..1), 32 rows each
    int wc = wid >> 1;       // N warp (0..3), WCW cols each

    // split-K resolution
    int kb = 0, ke = K;
    float* Cw = C;
    if (gridDim.z == 2) {
        if (blockIdx.z == 1) { kb = ksplit; Cw = C2; }
        else                 { ke = ksplit; }
    }
    const __half* srcs[3] = {Ah + kb, Al + kb, Bh + kb};
    const int toff[3] = {0, TILE_A, 2 * TILE_A};

    auto issue = [&](int kc, int stg) {
        int k0 = kc * 32;
        #pragma unroll
        for (int u = 0; u < U; u++) {
            int idx = tid + u * 256;
            int tile, row;
            if (idx < 256)      { tile = 0; row = idx >> 2; }
            else if (idx < 512) { tile = 1; row = (idx - 256) >> 2; }
            else                { tile = 2; row = (idx - 512) >> 2; }
            int c = idx & 3;
            int gr, maxr;
            if (tile < 2) { gr = bm + row; maxr = M; }
            else          { gr = bn + row; maxr = 1 << 30; }
            const __half* s = srcs[tile] +
                (size_t)gr * ((tile < 2) ? lda : ldb) + k0 + c * 8;
            uint32_t d = sb + stg * STG_B + toff[tile] + row * (TPITCH * 2) + c * 16;
            cp16(d, s, (gr < maxr) ? 16 : 0);
        }
        asm volatile("cp.async.commit_group;" ::: "memory");
    };

    float acc[2][NI][4] = {};
    int nT = (ke - kb) / 32;

    issue(0, 0);
    for (int t = 0; t < nT; t++) {
        int stg = t % STAGES;
        if (t + 1 < nT) {
            issue(t + 1, (t + 1) % STAGES);
            asm volatile("cp.async.wait_group 1;" ::: "memory");
        } else {
            asm volatile("cp.async.wait_group 0;" ::: "memory");
        }
        __syncthreads();

        uint32_t baseAH = sb + stg * STG_B + toff[0];
        uint32_t baseAL = sb + stg * STG_B + toff[1];
        uint32_t baseBH = sb + stg * STG_B + toff[2];

        #pragma unroll
        for (int ks = 0; ks < 2; ks++) {
            uint32_t aH[2][4], aL[2][4], bH[NP][4];
            int acol = (ks * 16 + (lane >> 4) * 8) * 2;
            int bcol = (ks * 16 + ((lane >> 3) & 1) * 8) * 2;
            #pragma unroll
            for (int mi = 0; mi < 2; mi++) {
                int arow = wr * 32 + mi * 16 + (lane & 15);
                ldsm_x4(aH[mi], baseAH + arow * (TPITCH * 2) + acol);
                ldsm_x4(aL[mi], baseAL + arow * (TPITCH * 2) + acol);
            }
            #pragma unroll
            for (int np = 0; np < NP; np++) {
                int brow = wc * WCW + np * 16 + ((lane >> 4) & 1) * 8 + (lane & 7);
                ldsm_x4(bH[np], baseBH + brow * (TPITCH * 2) + bcol);
            }
            #pragma unroll
            for (int mi = 0; mi < 2; mi++)
                #pragma unroll
                for (int ni = 0; ni < NI; ni++) {
                    const uint32_t* bh_ = &bH[ni >> 1][(ni & 1) * 2];
                    mma_f16(acc[mi][ni], aH[mi], bh_);
                    mma_f16(acc[mi][ni], aL[mi], bh_);
                }
        }
        __syncthreads();
    }

    // ---- epilogue ----
    float* pbuf = (float*)smem;               // 64 rows x 2 proj accumulators
    if (projOut) {
        for (int i = tid; i < 128; i += 256) pbuf[i] = 0.f;
        __syncthreads();
    }
    float pacc[2][2][2] = {};
    #pragma unroll
    for (int mi = 0; mi < 2; mi++) {
        #pragma unroll
        for (int half = 0; half < 2; half++) {
            int gm = bm + wr * 32 + mi * 16 + (lane >> 2) + half * 8;
            if (gm >= M) continue;
            bool cb = (cbias != nullptr) && (cnt[gm] > 0);
            #pragma unroll
            for (int ni = 0; ni < NI; ni++) {
                #pragma unroll
                for (int e = 0; e < 2; e++) {
                    int gn = bn + wc * WCW + ni * 8 + (lane & 3) * 2 + e;
                    float v = acc[mi][ni][half * 2 + e];
                    if (bias)    v += __ldg(&bias[gn]);
                    if (cb)      v += __ldg(&cbias[gn]);
                    if (addend)  v += addend[(size_t)gm * addld + gn];
                    if (addend2) v += addend2[(size_t)gm * addld + gn];
                    if (relu)    v = fmaxf(v, 0.f);
                    if (Cw) Cw[(size_t)gm * ldc + gn] = v;
                    if (outHi) {
                        __half h = __float2half(v);
                        outHi[(size_t)gm * 128 + gn] = h;
                        outLo[(size_t)gm * 128 + gn] =
                            __float2half(v - __half2float(h));
                    }
                    if (projOut) {
                        pacc[mi][half][0] = fmaf(v, __ldg(&projW[gn * 2 + 0]),
                                                 pacc[mi][half][0]);
                        pacc[mi][half][1] = fmaf(v, __ldg(&projW[gn * 2 + 1]),
                                                 pacc[mi][half][1]);
                    }
                }
            }
        }
    }
    if (projOut) {
        #pragma unroll
        for (int mi = 0; mi < 2; mi++)
            #pragma unroll
            for (int half = 0; half < 2; half++) {
                int rl = wr * 32 + mi * 16 + (lane >> 2) + half * 8;
                if (bm + rl < M) {
                    atomicAdd(&pbuf[rl * 2 + 0], pacc[mi][half][0]);
                    atomicAdd(&pbuf[rl * 2 + 1], pacc[mi][half][1]);
                }
            }
        __syncthreads();
        if (tid < 128) {
            int r = tid >> 1, c = tid & 1;
            if (bm + r < M) {
                float add = pbuf[tid] +
                            ((blockIdx.x == 0) ? __ldg(&projB[c]) : 0.f);
                atomicAdd(&projOut[(bm + r) * 2 + c], add);
            }
        }
    }
}

// ---------------- pairwise squared distances -------------------------------
__global__ void dist_kernel(const float* __restrict__ proj,
                            const int* __restrict__ idxs,
                            float* __restrict__ out) {
    int i = blockIdx.x * blockDim.x + threadIdx.x;
    if (i >= EE) return;
    int n  = i / (KK - 1);
    int nb = idxs[i];
    float dx = proj[n * 2 + 0] - proj[nb * 2 + 0];
    float dy = proj[n * 2 + 1] - proj[nb * 2 + 1];
    out[i] = dx * dx + dy * dy;
}

// ============================ launch ========================================
extern "C" void kernel_launch(void* const* d_in, const int* in_sizes, int n_in,
                              void* d_out, int out_size) {
    const float* x     = (const float*)d_in[0];
    const float* ea    = (const float*)d_in[1];
    const int*   idxs  = (const int*)  d_in[2];
    const float* l1mw1 = (const float*)d_in[3];   // [785,128]
    const float* l1mb1 = (const float*)d_in[4];
    const float* l1mw2 = (const float*)d_in[5];   // [128,784]
    const float* l1mb2 = (const float*)d_in[6];
    const float* l1nw1 = (const float*)d_in[7];   // [1568,128]
    const float* l1nb1 = (const float*)d_in[8];
    const float* l1nw2 = (const float*)d_in[9];   // [128,128]
    const float* l1nb2 = (const float*)d_in[10];
    const float* l2mw1 = (const float*)d_in[11];  // [129,128]
    const float* l2mb1 = (const float*)d_in[12];
    const float* l2mw2 = (const float*)d_in[13];  // [128,128]
    const float* l2mb2 = (const float*)d_in[14];
    const float* l2nw1 = (const float*)d_in[15];  // [256,128]
    const float* l2nb1 = (const float*)d_in[16];
    const float* l2nw2 = (const float*)d_in[17];  // [128,2]
    const float* l2nb2 = (const float*)d_in[18];
    float* out = (float*)d_out;

    __half *xh, *xl, *Wt1h, *Wf1h, *Wf2h, *Whth, *hbh, *hbl, *hidh, *hidl;
    float *XW, *XW2, *HW2, *proj, *bf1, *bf2, *bh;
    int *pos;
    cudaGetSymbolAddress((void**)&xh,   g_xh);
    cudaGetSymbolAddress((void**)&xl,   g_xl);
    cudaGetSymbolAddress((void**)&Wt1h, g_Wt1h);
    cudaGetSymbolAddress((void**)&Wf1h, g_Wf1h);
    cudaGetSymbolAddress((void**)&Wf2h, g_Wf2h);
    cudaGetSymbolAddress((void**)&Whth, g_Whth);
    cudaGetSymbolAddress((void**)&hbh,  g_hbh);
    cudaGetSymbolAddress((void**)&hbl,  g_hbl);
    cudaGetSymbolAddress((void**)&hidh, g_hidh);
    cudaGetSymbolAddress((void**)&hidl, g_hidl);
    cudaGetSymbolAddress((void**)&XW,   g_XW);
    cudaGetSymbolAddress((void**)&XW2,  g_XW2);
    cudaGetSymbolAddress((void**)&HW2,  g_HW2);
    cudaGetSymbolAddress((void**)&proj, g_proj);
    cudaGetSymbolAddress((void**)&bf1,  g_bf1);
    cudaGetSymbolAddress((void**)&bf2,  g_bf2);
    cudaGetSymbolAddress((void**)&bh,   g_bh);
    cudaGetSymbolAddress((void**)&pos,  g_pos);
    int* cnt = pos;   // degree == cnt

    // smem sizes per instantiation
    constexpr int SM_128_2 = 2 * (2 * TILE_A + 128 * TPITCH * 2);  // 40960
    constexpr int SM_64_2  = 2 * (2 * TILE_A + 64 * TPITCH * 2);   // 30720
    cudaFuncSetAttribute((const void*)tgemm<128,2,3>,
                         cudaFuncAttributeMaxDynamicSharedMemorySize, SM_128_2);
    cudaFuncSetAttribute((const void*)tgemm<64,2,3>,
                         cudaFuncAttributeMaxDynamicSharedMemorySize, SM_64_2);

    // ---- memsets: degree counters + proj accumulator ----
    cudaMemsetAsync(pos, 0, NN * sizeof(int));
    cudaMemsetAsync(proj, 0, NN * 2 * sizeof(float));

    // ---- fold argument pack ----
    FoldArgs fa;
    fa.A[0] = l1mw2;  fa.avec[0] = l1mb2;  fa.B[0] = l1nw1 + (size_t)DD * HH;
    fa.oh[0] = Wf1h;  fa.bf[0] = bf1;
    fa.Kd[0] = DD;    fa.row_off[0] = 0;
    fa.A[1] = l2mw2;  fa.avec[1] = l2mb2;  fa.B[1] = l2nw1 + (size_t)HH * HH;
    fa.oh[1] = Wf2h;  fa.bf[1] = bf2;
    fa.Kd[1] = HH;    fa.row_off[1] = 0;
    fa.A[2] = l1nw2;  fa.avec[2] = l1nb2;  fa.B[2] = l2mw1;
    fa.oh[2] = Whth;  fa.bf[2] = bh;
    fa.Kd[2] = HH;    fa.row_off[2] = 0;
    fa.A[3] = l1nw2;  fa.avec[3] = l1nb2;  fa.B[3] = l2nw1;
    fa.oh[3] = Whth;  fa.bf[3] = bh + 128;
    fa.Kd[3] = HH;    fa.row_off[3] = 128;

    // ---- fixed-stride bucket fill (no count, no scan) ----
    fill_kernel<<<(EE + 255) / 256, 256>>>(idxs, ea);
    // ---- prep: conv + convT + folds in ONE launch ----
    prep_mega<<<PB_TOTAL, 256>>>(x, l1mw1, l1nw1, xh, xl, Wt1h, fa);

    // ---- layer 1 ----
    // XW (+XW2 split-K) = x @ [W1x_msg | W1a_node]   [N,256]
    // (K=800; MB=3 / regs=80 -- measured best)
    tgemm<128,2,3><<<dim3(2, 157, 2), 256, SM_128_2>>>(
        xh, xl, KPAD, Wt1h, KPAD, KPAD, NN,
        XW, XW2, 384, 256,
        nullptr, nullptr, nullptr,
        nullptr, nullptr, 0, 0,
        nullptr, nullptr, nullptr, nullptr, nullptr);
    // hbar = mean_e relu((XW+XW2)[:, :128][src] + a*we1 + b1)   (fp16 pair)
    edge_agg<<<(NN * HH + 255) / 256, 256>>>(XW, XW2, 256,
                                             l1mw1 + (size_t)DD * HH,
                                             l1mb1, hbh, hbl);
    // hidden1 = relu(hbar@Wf1 + (XW+XW2)[:,128:] + l1nb1 + [cnt>0]*bf1) -> fp16
    tgemm<64,2,3><<<dim3(2, 157, 1), 256, SM_64_2>>>(
        hbh, hbl, HH, Wf1h, HH, HH, NN,
        nullptr, nullptr, 0, 0,
        l1nb1, bf1, cnt,
        XW + 128, XW2 + 128, 256, 1,
        hidh, hidl, nullptr, nullptr, nullptr);

    // ---- layer 2 (intermediate h folded away) ----
    // HW2 = hidden1 @ Wh + bh   [N,256]  BN=64 -> grid (4,157)
    tgemm<64,2,3><<<dim3(4, 157, 1), 256, SM_64_2>>>(
        hidh, hidl, HH, Whth, HH, HH, NN,
        HW2, nullptr, 0, 256,
        bh, nullptr, nullptr,
        nullptr, nullptr, 0, 0,
        nullptr, nullptr, nullptr, nullptr, nullptr);
    // hbar2 = mean_e relu(HW2[:, :128][src] + a*we2 + b1)
    edge_agg<<<(NN * HH + 255) / 256, 256>>>(HW2, nullptr, 256,
                                             l2mw1 + (size_t)HH * HH,
                                             l2mb1, hbh, hbl);
    // hidden2 = relu(hbar2@Wf2 + HW2[:,128:] + l2nb1 + [cnt>0]*bf2) -> fused
    // proj via global atomicAdd (proj pre-zeroed); BN=64 -> grid (2,157)
    tgemm<64,2,3><<<dim3(2, 157, 1), 256, SM_64_2>>>(
        hbh, hbl, HH, Wf2h, HH, HH, NN,
        nullptr, nullptr, 0, 0,
        l2nb1, bf2, cnt,
        HW2 + 128, nullptr, 256, 1,
        nullptr, nullptr, l2nw2, l2nb2, proj);

    // ---- output ----
    dist_kernel<<<(EE + 255) / 256, 256>>>(proj, idxs, out);
}

// round 17
// speedup vs baseline: 1.0994x; 1.0629x over previous
#include <cuda_runtime.h>
#include <cuda_fp16.h>
#include <cstdint>

// Problem constants (fixed by the reference)
#define NN 10000          // nodes
#define DD 784            // input feat dim
#define KPAD 800          // DD padded to multiple of 32 (pad cols stay zero)
#define KK 16             // neighbors+1
#define EE (NN * (KK-1))  // edges = 150000
#define HH 128            // hidden width
#define CAP 96            // fixed bucket capacity per node (P(deg>=96) ~ 0)

// ============================ scratch globals ===============================
// Numeric scheme (FROZEN since R12): A-side exact via fp16 hi/lo pair;
// B-side (weights) single fp16. GEMM computes (Ah+Al)@Bh -> 2 MMA products.
__device__ __align__(256) __half g_xh   [NN * KPAD];
__device__ __align__(256) __half g_xl   [NN * KPAD];
__device__ __align__(256) __half g_Wt1h [256 * KPAD]; // [l1 msgW1x^T ; l1 nodeW1a^T]
__device__ __align__(256) __half g_Wf1h [HH * HH];    // (l1 msgW2 @ l1 nodeW1b)^T
__device__ __align__(256) __half g_Wf2h [HH * HH];
__device__ __align__(256) __half g_Whth [256 * HH];   // (l1 nodeW2 @ [l2 W1x | l2 W1a])^T
__device__ __align__(256) float g_bf1[HH];
__device__ __align__(256) float g_bf2[HH];
__device__ __align__(256) float g_bh [256];
__device__ __align__(256) float g_XW  [NN * 256];   // split-K part 0
__device__ __align__(256) float g_XW2 [NN * 256];   // split-K part 1
__device__ __align__(256) float g_HW2 [NN * 256];
__device__ __align__(256) __half g_hbh [NN * HH];     // hbar hi/lo
__device__ __align__(256) __half g_hbl [NN * HH];
__device__ __align__(256) __half g_hidh[NN * HH];     // hidden hi/lo
__device__ __align__(256) __half g_hidl[NN * HH];
__device__ __align__(256) float g_proj[NN * 2];
__device__ int   g_pos [NN];            // degree counters (also the cnt array)
__device__ __align__(256) float g_bucket[NN * CAP];   // fixed-stride edge lists

// ============================ prep megakernel ===============================
struct FoldArgs {
    const float* A[4];
    const float* avec[4];
    const float* B[4];
    __half* oh[4];
    float* bf[4];
    int Kd[4];
    int row_off[4];
};

#define PB_FILL  586
#define PB_CONV  7657
#define PB_CONVT 1024     // 2 weights x (4 k-blocks x 128 n)
#define PB_FOLD  516      // 4 folds x 129 rows
#define PB_TOTAL (PB_FILL + PB_CONV + PB_CONVT + PB_FOLD)

__global__ void __launch_bounds__(256)
prep_mega(const int* __restrict__ idxs, const float* __restrict__ ea,
          const float* __restrict__ x,
          const float* __restrict__ Wc0, const float* __restrict__ Wc1,
          __half* __restrict__ xh, __half* __restrict__ xl,
          __half* __restrict__ Wt1h, FoldArgs fa) {
    __shared__ float red[256];
    int b = blockIdx.x, tid = threadIdx.x;

    if (b < PB_FILL) {                        // ---- bucket fill ----
        int e = b * 256 + tid;
        if (e < EE) {
            int s = idxs[e];
            int p = atomicAdd(&g_pos[s], 1);
            if (p < CAP) g_bucket[s * CAP + p] = ea[e];
        }
        return;
    }
    b -= PB_FILL;
    if (b < PB_CONV) {                        // ---- x fp16 hi/lo split ----
        int i = b * 256 + tid;
        if (i >= NN * (DD / 4)) return;
        int row = i / (DD / 4), c = i % (DD / 4);
        float4 v = ((const float4*)(x + (size_t)row * DD))[c];
        __half h0 = __float2half(v.x), h1 = __float2half(v.y);
        __half h2 = __float2half(v.z), h3 = __float2half(v.w);
        __half l0 = __float2half(v.x - __half2float(h0));
        __half l1 = __float2half(v.y - __half2float(h1));
        __half l2 = __float2half(v.z - __half2float(h2));
        __half l3 = __float2half(v.w - __half2float(h3));
        size_t o = (size_t)row * KPAD + c * 4;
        *(__half2*)(xh + o)     = __half2(h0, h1);
        *(__half2*)(xh + o + 2) = __half2(h2, h3);
        *(__half2*)(xl + o)     = __half2(l0, l1);
        *(__half2*)(xl + o + 2) = __half2(l2, l3);
        return;
    }
    b -= PB_CONV;
    if (b < PB_CONVT) {                       // ---- W1 transpose, fp16 hi ----
        int z = b >> 9;                       // which weight (0/1)
        int rem = b & 511;
        int kb = rem & 3, n = rem >> 2;
        int k = kb * 256 + tid;
        if (k >= DD) return;
        const float* W = z ? Wc1 : Wc0;
        float v = W[(size_t)k * 128 + n];
        Wt1h[(size_t)(z * 128 + n) * KPAD + k] = __float2half(v);
        return;
    }
    b -= PB_CONVT;
    {                                         // ---- weight folds (fp16 hi) ----
        int f = b / 129, i = b % 129;
        int j = tid & 127, kq = tid >> 7;     // 2-way K split
        int Kd = fa.Kd[f];
        const float* arow = (i < 128) ? (fa.A[f] + (size_t)i * Kd) : fa.avec[f];
        const float* B = fa.B[f];
        int chunk = (Kd + 1) >> 1;
        int k0 = kq * chunk, k1 = min(Kd, k0 + chunk);
        float s = 0.f;
        #pragma unroll 4
        for (int k = k0; k < k1; k++)
            s = fmaf(__ldg(&arow[k]), B[(size_t)k * HH + j], s);
        red[tid] = s;
        __syncthreads();
        if (kq == 0) {
            s = red[j] + red[128 + j];
            if (i < 128)
                fa.oh[f][(size_t)(fa.row_off[f] + j) * HH + i] = __float2half(s);
            else
                fa.bf[f][j] = s;
        }
        return;
    }
}

// per-(node, 4-col) edge aggregation; optional second split-K buffer.
// hbar[m,j] = mean_e relu(xwA[m,j] (+ xwB[m,j]) + b[j] + a_e*we[j])
__global__ void edge_agg(const float* __restrict__ xwA,
                         const float* __restrict__ xwB, int ld,
                         const float* __restrict__ we,
                         const float* __restrict__ b,
                         __half* __restrict__ oh,
                         __half* __restrict__ ol) {
    int idx = blockIdx.x * blockDim.x + threadIdx.x;
    if (idx >= NN * 32) return;
    int m = idx >> 5;
    int j = (idx & 31) * 4;
    int deg = min(g_pos[m], CAP);
    const float* bk = g_bucket + m * CAP;

    float4 xj = *(const float4*)(xwA + (size_t)m * ld + j);
    if (xwB) {
        float4 x2 = *(const float4*)(xwB + (size_t)m * ld + j);
        xj.x += x2.x; xj.y += x2.y; xj.z += x2.z; xj.w += x2.w;
    }
    float4 bb = *(const float4*)(b + j);
    xj.x += bb.x; xj.y += bb.y; xj.z += bb.z; xj.w += bb.w;
    float4 wj = *(const float4*)(we + j);

    float4 s = make_float4(0.f, 0.f, 0.f, 0.f);
    #pragma unroll 2
    for (int t = 0; t < deg; t++) {
        float a = bk[t];
        s.x += fmaxf(fmaf(a, wj.x, xj.x), 0.f);
        s.y += fmaxf(fmaf(a, wj.y, xj.y), 0.f);
        s.z += fmaxf(fmaf(a, wj.z, xj.z), 0.f);
        s.w += fmaxf(fmaf(a, wj.w, xj.w), 0.f);
    }
    float inv = deg ? 1.f / (float)deg : 0.f;
    float v0 = s.x * inv, v1 = s.y * inv, v2 = s.z * inv, v3 = s.w * inv;
    __half h0 = __float2half(v0), h1 = __float2half(v1);
    __half h2 = __float2half(v2), h3 = __float2half(v3);
    size_t o = (size_t)m * HH + j;
    *(__half2*)(oh + o)     = __half2(h0, h1);
    *(__half2*)(oh + o + 2) = __half2(h2, h3);
    *(__half2*)(ol + o)     = __half2(__float2half(v0 - __half2float(h0)),
                                      __float2half(v1 - __half2float(h1)));
    *(__half2*)(ol + o + 2) = __half2(__float2half(v2 - __half2float(h2)),
                                      __float2half(v3 - __half2float(h3)));
}

// ============================ mma.sync GEMM ================================
// C[M,Ntot] = (Ah+Al)[M,K] @ Bh^T (B stored [Ntot][K] fp16); 2-product.
// Block tile 64xBN, BK=32, 8 warps (2 M x 4 N), STAGES-deep cp.async pipeline,
// MB min-blocks occupancy bound. Optional split-K via gridDim.z==2.
// Fused projection (projOut != nullptr) accumulates partial row-projections
// via global atomicAdd (projOut must be pre-zeroed; projB added by block x==0).
#define TPITCH 40                      // fp16 pitch (80 B) per smem tile row
#define TILE_A (64 * TPITCH * 2)       // 5120 B

__device__ __forceinline__ uint32_t smem_u32(const void* p) {
    uint32_t a;
    asm("{ .reg .u64 t; cvta.to.shared.u64 t, %1; cvt.u32.u64 %0, t; }"
        : "=r"(a) : "l"(p));
    return a;
}
__device__ __forceinline__ void cp16(uint32_t dst, const void* src, int sz) {
    asm volatile("cp.async.cg.shared.global [%0], [%1], 16, %2;"
        :: "r"(dst), "l"(src), "r"(sz) : "memory");
}
__device__ __forceinline__ void ldsm_x4(uint32_t* r, uint32_t a) {
    asm volatile("ldmatrix.sync.aligned.m8n8.x4.shared.b16 {%0,%1,%2,%3}, [%4];"
        : "=r"(r[0]), "=r"(r[1]), "=r"(r[2]), "=r"(r[3]) : "r"(a));
}
__device__ __forceinline__ void mma_f16(float* c, const uint32_t* a, const uint32_t* b) {
    asm volatile("mma.sync.aligned.m16n8k16.row.col.f32.f16.f16.f32 "
        "{%0,%1,%2,%3}, {%4,%5,%6,%7}, {%8,%9}, {%0,%1,%2,%3};"
        : "+f"(c[0]), "+f"(c[1]), "+f"(c[2]), "+f"(c[3])
        : "r"(a[0]), "r"(a[1]), "r"(a[2]), "r"(a[3]), "r"(b[0]), "r"(b[1]));
}

template<int BN, int STAGES, int MB>
__global__ void __launch_bounds__(256, MB)
tgemm(const __half* __restrict__ Ah, const __half* __restrict__ Al,
      int lda,
      const __half* __restrict__ Bh, int ldb, int K, int M,
      float* __restrict__ C, float* __restrict__ C2, int ksplit, int ldc,
      const float* __restrict__ bias,
      const float* __restrict__ cbias, const int* __restrict__ cnt,
      const float* __restrict__ addend, const float* __restrict__ addend2,
      int addld, int relu,
      __half* __restrict__ outHi, __half* __restrict__ outLo,
      const float* __restrict__ projW, const float* __restrict__ projB,
      float* __restrict__ projOut) {
    constexpr int TILE_Bn = BN * TPITCH * 2;
    constexpr int STG_B = 2 * TILE_A + TILE_Bn;
    constexpr int NI = BN / 32;        // fragment column groups
    constexpr int NP = NI / 2;         // ldsm_x4 B loads per ks
    constexpr int WCW = BN / 4;        // cols per N-warp
    constexpr int NCH = 512 + BN * 4;  // 16B chunks per stage
    constexpr int U = NCH / 256;

    extern __shared__ char smem[];
    uint32_t sb = smem_u32(smem);
    int tid = threadIdx.x;
    int wid = tid >> 5, lane = tid & 31;
    int bm = blockIdx.y * 64;
    int bn = blockIdx.x * BN;
    int wr = wid & 1;        // M warp (0..1), 32 rows each
    int wc = wid >> 1;       // N warp (0..3), WCW cols each

    // split-K resolution
    int kb = 0, ke = K;
    float* Cw = C;
    if (gridDim.z == 2) {
        if (blockIdx.z == 1) { kb = ksplit; Cw = C2; }
        else                 { ke = ksplit; }
    }
    const __half* srcs[3] = {Ah + kb, Al + kb, Bh + kb};
    const int toff[3] = {0, TILE_A, 2 * TILE_A};

    auto issue = [&](int kc, int stg) {
        int k0 = kc * 32;
        #pragma unroll
        for (int u = 0; u < U; u++) {
            int idx = tid + u * 256;
            int tile, row;
            if (idx < 256)      { tile = 0; row = idx >> 2; }
            else if (idx < 512) { tile = 1; row = (idx - 256) >> 2; }
            else                { tile = 2; row = (idx - 512) >> 2; }
            int c = idx & 3;
            int gr, maxr;
            if (tile < 2) { gr = bm + row; maxr = M; }
            else          { gr = bn + row; maxr = 1 << 30; }
            const __half* s = srcs[tile] +
                (size_t)gr * ((tile < 2) ? lda : ldb) + k0 + c * 8;
            uint32_t d = sb + stg * STG_B + toff[tile] + row * (TPITCH * 2) + c * 16;
            cp16(d, s, (gr < maxr) ? 16 : 0);
        }
        asm volatile("cp.async.commit_group;" ::: "memory");
    };

    float acc[2][NI][4] = {};
    int nT = (ke - kb) / 32;

    issue(0, 0);
    for (int t = 0; t < nT; t++) {
        int stg = t % STAGES;
        if (t + 1 < nT) {
            issue(t + 1, (t + 1) % STAGES);
            asm volatile("cp.async.wait_group 1;" ::: "memory");
        } else {
            asm volatile("cp.async.wait_group 0;" ::: "memory");
        }
        __syncthreads();

        uint32_t baseAH = sb + stg * STG_B + toff[0];
        uint32_t baseAL = sb + stg * STG_B + toff[1];
        uint32_t baseBH = sb + stg * STG_B + toff[2];

        #pragma unroll
        for (int ks = 0; ks < 2; ks++) {
            uint32_t aH[2][4], aL[2][4], bH[NP][4];
            int acol = (ks * 16 + (lane >> 4) * 8) * 2;
            int bcol = (ks * 16 + ((lane >> 3) & 1) * 8) * 2;
            #pragma unroll
            for (int mi = 0; mi < 2; mi++) {
                int arow = wr * 32 + mi * 16 + (lane & 15);
                ldsm_x4(aH[mi], baseAH + arow * (TPITCH * 2) + acol);
                ldsm_x4(aL[mi], baseAL + arow * (TPITCH * 2) + acol);
            }
            #pragma unroll
            for (int np = 0; np < NP; np++) {
                int brow = wc * WCW + np * 16 + ((lane >> 4) & 1) * 8 + (lane & 7);
                ldsm_x4(bH[np], baseBH + brow * (TPITCH * 2) + bcol);
            }
            #pragma unroll
            for (int mi = 0; mi < 2; mi++)
                #pragma unroll
                for (int ni = 0; ni < NI; ni++) {
                    const uint32_t* bh_ = &bH[ni >> 1][(ni & 1) * 2];
                    mma_f16(acc[mi][ni], aH[mi], bh_);
                    mma_f16(acc[mi][ni], aL[mi], bh_);
                }
        }
        __syncthreads();
    }

    // ---- epilogue ----
    float* pbuf = (float*)smem;               // 64 rows x 2 proj accumulators
    if (projOut) {
        for (int i = tid; i < 128; i += 256) pbuf[i] = 0.f;
        __syncthreads();
    }
    float pacc[2][2][2] = {};
    #pragma unroll
    for (int mi = 0; mi < 2; mi++) {
        #pragma unroll
        for (int half = 0; half < 2; half++) {
            int gm = bm + wr * 32 + mi * 16 + (lane >> 2) + half * 8;
            if (gm >= M) continue;
            bool cb = (cbias != nullptr) && (cnt[gm] > 0);
            #pragma unroll
            for (int ni = 0; ni < NI; ni++) {
                #pragma unroll
                for (int e = 0; e < 2; e++) {
                    int gn = bn + wc * WCW + ni * 8 + (lane & 3) * 2 + e;
                    float v = acc[mi][ni][half * 2 + e];
                    if (bias)    v += __ldg(&bias[gn]);
                    if (cb)      v += __ldg(&cbias[gn]);
                    if (addend)  v += addend[(size_t)gm * addld + gn];
                    if (addend2) v += addend2[(size_t)gm * addld + gn];
                    if (relu)    v = fmaxf(v, 0.f);
                    if (Cw) Cw[(size_t)gm * ldc + gn] = v;
                    if (outHi) {
                        __half h = __float2half(v);
                        outHi[(size_t)gm * 128 + gn] = h;
                        outLo[(size_t)gm * 128 + gn] =
                            __float2half(v - __half2float(h));
                    }
                    if (projOut) {
                        pacc[mi][half][0] = fmaf(v, __ldg(&projW[gn * 2 + 0]),
                                                 pacc[mi][half][0]);
                        pacc[mi][half][1] = fmaf(v, __ldg(&projW[gn * 2 + 1]),
                                                 pacc[mi][half][1]);
                    }
                }
            }
        }
    }
    if (projOut) {
        #pragma unroll
        for (int mi = 0; mi < 2; mi++)
            #pragma unroll
            for (int half = 0; half < 2; half++) {
                int rl = wr * 32 + mi * 16 + (lane >> 2) + half * 8;
                if (bm + rl < M) {
                    atomicAdd(&pbuf[rl * 2 + 0], pacc[mi][half][0]);
                    atomicAdd(&pbuf[rl * 2 + 1], pacc[mi][half][1]);
                }
            }
        __syncthreads();
        if (tid < 128) {
            int r = tid >> 1, c = tid & 1;
            if (bm + r < M) {
                float add = pbuf[tid] +
                            ((blockIdx.x == 0) ? __ldg(&projB[c]) : 0.f);
                atomicAdd(&projOut[(bm + r) * 2 + c], add);
            }
        }
    }
}

// ---------------- pairwise squared distances -------------------------------
__global__ void dist_kernel(const float* __restrict__ proj,
                            const int* __restrict__ idxs,
                            float* __restrict__ out) {
    int i = blockIdx.x * blockDim.x + threadIdx.x;
    if (i >= EE) return;
    int n  = i / (KK - 1);
    int nb = idxs[i];
    float dx = proj[n * 2 + 0] - proj[nb * 2 + 0];
    float dy = proj[n * 2 + 1] - proj[nb * 2 + 1];
    out[i] = dx * dx + dy * dy;
}

// ============================ launch ========================================
extern "C" void kernel_launch(void* const* d_in, const int* in_sizes, int n_in,
                              void* d_out, int out_size) {
    const float* x     = (const float*)d_in[0];
    const float* ea    = (const float*)d_in[1];
    const int*   idxs  = (const int*)  d_in[2];
    const float* l1mw1 = (const float*)d_in[3];   // [785,128]
    const float* l1mb1 = (const float*)d_in[4];
    const float* l1mw2 = (const float*)d_in[5];   // [128,784]
    const float* l1mb2 = (const float*)d_in[6];
    const float* l1nw1 = (const float*)d_in[7];   // [1568,128]
    const float* l1nb1 = (const float*)d_in[8];
    const float* l1nw2 = (const float*)d_in[9];   // [128,128]
    const float* l1nb2 = (const float*)d_in[10];
    const float* l2mw1 = (const float*)d_in[11];  // [129,128]
    const float* l2mb1 = (const float*)d_in[12];
    const float* l2mw2 = (const float*)d_in[13];  // [128,128]
    const float* l2mb2 = (const float*)d_in[14];
    const float* l2nw1 = (const float*)d_in[15];  // [256,128]
    const float* l2nb1 = (const float*)d_in[16];
    const float* l2nw2 = (const float*)d_in[17];  // [128,2]
    const float* l2nb2 = (const float*)d_in[18];
    float* out = (float*)d_out;

    __half *xh, *xl, *Wt1h, *Wf1h, *Wf2h, *Whth, *hbh, *hbl, *hidh, *hidl;
    float *XW, *XW2, *HW2, *proj, *bf1, *bf2, *bh;
    int *pos;
    cudaGetSymbolAddress((void**)&xh,   g_xh);
    cudaGetSymbolAddress((void**)&xl,   g_xl);
    cudaGetSymbolAddress((void**)&Wt1h, g_Wt1h);
    cudaGetSymbolAddress((void**)&Wf1h, g_Wf1h);
    cudaGetSymbolAddress((void**)&Wf2h, g_Wf2h);
    cudaGetSymbolAddress((void**)&Whth, g_Whth);
    cudaGetSymbolAddress((void**)&hbh,  g_hbh);
    cudaGetSymbolAddress((void**)&hbl,  g_hbl);
    cudaGetSymbolAddress((void**)&hidh, g_hidh);
    cudaGetSymbolAddress((void**)&hidl, g_hidl);
    cudaGetSymbolAddress((void**)&XW,   g_XW);
    cudaGetSymbolAddress((void**)&XW2,  g_XW2);
    cudaGetSymbolAddress((void**)&HW2,  g_HW2);
    cudaGetSymbolAddress((void**)&proj, g_proj);
    cudaGetSymbolAddress((void**)&bf1,  g_bf1);
    cudaGetSymbolAddress((void**)&bf2,  g_bf2);
    cudaGetSymbolAddress((void**)&bh,   g_bh);
    cudaGetSymbolAddress((void**)&pos,  g_pos);
    int* cnt = pos;   // degree == cnt

    // smem sizes per instantiation
    constexpr int SM_128_2 = 2 * (2 * TILE_A + 128 * TPITCH * 2);  // 40960
    constexpr int SM_64_2  = 2 * (2 * TILE_A + 64 * TPITCH * 2);   // 30720
    cudaFuncSetAttribute((const void*)tgemm<128,2,3>,
                         cudaFuncAttributeMaxDynamicSharedMemorySize, SM_128_2);
    cudaFuncSetAttribute((const void*)tgemm<64,2,3>,
                         cudaFuncAttributeMaxDynamicSharedMemorySize, SM_64_2);

    // ---- memsets: degree counters + proj accumulator ----
    cudaMemsetAsync(pos, 0, NN * sizeof(int));
    cudaMemsetAsync(proj, 0, NN * 2 * sizeof(float));

    // ---- fold argument pack ----
    FoldArgs fa;
    fa.A[0] = l1mw2;  fa.avec[0] = l1mb2;  fa.B[0] = l1nw1 + (size_t)DD * HH;
    fa.oh[0] = Wf1h;  fa.bf[0] = bf1;
    fa.Kd[0] = DD;    fa.row_off[0] = 0;
    fa.A[1] = l2mw2;  fa.avec[1] = l2mb2;  fa.B[1] = l2nw1 + (size_t)HH * HH;
    fa.oh[1] = Wf2h;  fa.bf[1] = bf2;
    fa.Kd[1] = HH;    fa.row_off[1] = 0;
    fa.A[2] = l1nw2;  fa.avec[2] = l1nb2;  fa.B[2] = l2mw1;
    fa.oh[2] = Whth;  fa.bf[2] = bh;
    fa.Kd[2] = HH;    fa.row_off[2] = 0;
    fa.A[3] = l1nw2;  fa.avec[3] = l1nb2;  fa.B[3] = l2nw1;
    fa.oh[3] = Whth;  fa.bf[3] = bh + 128;
    fa.Kd[3] = HH;    fa.row_off[3] = 128;

    // ---- prep: fill + conv + convT + folds in ONE launch ----
    prep_mega<<<PB_TOTAL, 256>>>(idxs, ea, x, l1mw1, l1nw1, xh, xl, Wt1h, fa);

    // ---- layer 1 ----
    // XW (+XW2 split-K) = x @ [W1x_msg | W1a_node]   [N,256]
    // (K=800; MB=3 / regs=80 -- measured best)
    tgemm<128,2,3><<<dim3(2, 157, 2), 256, SM_128_2>>>(
        xh, xl, KPAD, Wt1h, KPAD, KPAD, NN,
        XW, XW2, 384, 256,
        nullptr, nullptr, nullptr,
        nullptr, nullptr, 0, 0,
        nullptr, nullptr, nullptr, nullptr, nullptr);
    // hbar = mean_e relu((XW+XW2)[:, :128][src] + a*we1 + b1)   (fp16 pair)
    edge_agg<<<(NN * 32 + 255) / 256, 256>>>(XW, XW2, 256,
                                             l1mw1 + (size_t)DD * HH,
                                             l1mb1, hbh, hbl);
    // hidden1 = relu(hbar@Wf1 + (XW+XW2)[:,128:] + l1nb1 + [cnt>0]*bf1) -> fp16
    tgemm<64,2,3><<<dim3(2, 157, 1), 256, SM_64_2>>>(
        hbh, hbl, HH, Wf1h, HH, HH, NN,
        nullptr, nullptr, 0, 0,
        l1nb1, bf1, cnt,
        XW + 128, XW2 + 128, 256, 1,
        hidh, hidl, nullptr, nullptr, nullptr);

    // ---- layer 2 (intermediate h folded away) ----
    // HW2 = hidden1 @ Wh + bh   [N,256]  BN=64 -> grid (4,157)
    tgemm<64,2,3><<<dim3(4, 157, 1), 256, SM_64_2>>>(
        hidh, hidl, HH, Whth, HH, HH, NN,
        HW2, nullptr, 0, 256,
        bh, nullptr, nullptr,
        nullptr, nullptr, 0, 0,
        nullptr, nullptr, nullptr, nullptr, nullptr);
    // hbar2 = mean_e relu(HW2[:, :128][src] + a*we2 + b1)
    edge_agg<<<(NN * 32 + 255) / 256, 256>>>(HW2, nullptr, 256,
                                             l2mw1 + (size_t)HH * HH,
                                             l2mb1, hbh, hbl);
    // hidden2 = relu(hbar2@Wf2 + HW2[:,128:] + l2nb1 + [cnt>0]*bf2) -> fused
    // proj via global atomicAdd (proj pre-zeroed); BN=64 -> grid (2,157)
    tgemm<64,2,3><<<dim3(2, 157, 1), 256, SM_64_2>>>(
        hbh, hbl, HH, Wf2h, HH, HH, NN,
        nullptr, nullptr, 0, 0,
        l2nb1, bf2, cnt,
        HW2 + 128, nullptr, 256, 1,
        nullptr, nullptr, l2nw2, l2nb2, proj);

    // ---- output ----
    dist_kernel<<<(EE + 255) / 256, 256>>>(proj, idxs, out);
}